// round 2
// baseline (speedup 1.0000x reference)
#include <cuda_runtime.h>
#include <cstdint>

typedef unsigned long long ull;

#define NBT   3200          // B*T = 64*50
#define NND   22            // nodes
#define NCH   64            // C = O = 64
#define SLICE (NND*NCH)     // 1408
#define TOT   (NBT*SLICE)   // 4,505,600
#define MAXNZ 484

// ---------------- device scratch (static, no allocs) ----------------
__device__ float g_hbuf0[TOT];
__device__ float g_hbuf1[TOT];
__device__ float g_hbuf2[TOT];
__device__ float g_pre2[TOT];
__device__ float g_part1[6*64*NBT];
__device__ float g_part2[2*64*NBT];
__device__ float g_scale1[192], g_shift1[192];
__device__ float g_scale2[64],  g_shift2[64];
__device__ float g_Wt[5*4096];          // [g][o][c], g: W0s,W1s,W0c,W1c,Wdis
__device__ float g_diag[2][NND*NCH];    // A[o,i,i], stored [i*64+o]
__device__ float g_offv[2][MAXNZ*NCH];  // off-diag values [m*64+o]
__device__ int   g_offcol[2][MAXNZ];
__device__ int   g_rowptr[2][NND+1];

// ---------------- f32x2 helpers ----------------
__device__ __forceinline__ ull ffma2(ull a, ull b, ull c){
    ull d;
    asm("fma.rn.f32x2 %0, %1, %2, %3;" : "=l"(d) : "l"(a), "l"(b), "l"(c));
    return d;
}
__device__ __forceinline__ float hsum2(ull v){
    float a, b;
    asm("mov.b64 {%0, %1}, %2;" : "=f"(a), "=f"(b) : "l"(v));
    return a + b;
}

// ---------------- prep: softmax adjacencies (sparse) + weight transpose ----------------
__global__ void k_prep(const float* __restrict__ e_sym, const int* __restrict__ rows_sym,
                       const int* __restrict__ cols_sym, int nnz_sym,
                       const float* __restrict__ e_con, const int* __restrict__ rows_con,
                       const int* __restrict__ cols_con, int nnz_con,
                       const float* __restrict__ W_sym, const float* __restrict__ W_con,
                       const float* __restrict__ W_dis)
{
    int blk = blockIdx.x, tid = threadIdx.x;
    if (blk == 2){
        // transpose 5 (64,64) weight matrices to [o][c]
        for (int p = tid; p < 5*4096; p += 256){
            int g = p >> 12, rem = p & 4095, c = rem >> 6, o = rem & 63;
            float v;
            if (g < 2)      v = W_sym[g*4096 + c*64 + o];
            else if (g < 4) v = W_con[(g-2)*4096 + c*64 + o];
            else            v = W_dis[c*64 + o];
            g_Wt[g*4096 + o*64 + c] = v;
        }
        return;
    }
    int br = blk;
    const float* e   = br ? e_con   : e_sym;
    const int* rows  = br ? rows_con : rows_sym;
    const int* cols  = br ? cols_con : cols_sym;
    int nnz          = br ? nnz_con : nnz_sym;

    __shared__ float sden[NND*NCH];
    __shared__ int   smap[512];

    for (int p = tid; p < NND*NCH; p += 256) g_diag[br][p] = 0.f;
    __syncthreads();

    if (tid == 0){
        int m = 0;
        for (int k = 0; k < nnz; k++){
            int r = rows[k], c = cols[k];
            if (c != r){ smap[k] = m; g_offcol[br][m] = c; m++; }
            else smap[k] = -1;
        }
        for (int i = 0; i <= NND; i++){
            int cnt = 0;
            for (int k = 0; k < nnz; k++)
                if (cols[k] != rows[k] && rows[k] < i) cnt++;
            g_rowptr[br][i] = cnt;
        }
    }
    __syncthreads();

    // softmax denominators per (row i, channel o)
    for (int p = tid; p < NND*NCH; p += 256){
        int i = p >> 6, o = p & 63;
        float s = 0.f;
        for (int k = 0; k < nnz; k++)
            if (rows[k] == i) s += expf(e[o*nnz + k]);
        sden[p] = s;
    }
    __syncthreads();

    for (int p = tid; p < 64*nnz; p += 256){
        int k = p >> 6, o = p & 63;
        int r = rows[k];
        float v = expf(e[o*nnz + k]) / sden[r*64 + o];
        int m = smap[k];
        if (m < 0) g_diag[br][r*64 + o] = v;
        else       g_offv[br][m*64 + o] = v;
    }
}

// ---------------- small GEMM: 6 rows x 64 out for one thread (packed f32x2) ----------------
__device__ __forceinline__ void gemm6(const float* __restrict__ src,
                                      const float* __restrict__ wrow,
                                      int quad, float out[6])
{
    ull acc[6];
#pragma unroll
    for (int r = 0; r < 6; r++) acc[r] = 0ull;
    const ulonglong2* w2 = reinterpret_cast<const ulonglong2*>(wrow);
#pragma unroll
    for (int cq = 0; cq < 16; cq++){
        ulonglong2 w = __ldg(w2 + cq);
#pragma unroll
        for (int r = 0; r < 6; r++){
            int i = quad + 4*r;
            if (i < NND){
                ulonglong2 xv = *reinterpret_cast<const ulonglong2*>(src + i*NCH + cq*4);
                acc[r] = ffma2(xv.x, w.x, acc[r]);
                acc[r] = ffma2(xv.y, w.y, acc[r]);
            }
        }
    }
#pragma unroll
    for (int r = 0; r < 6; r++) out[r] = hsum2(acc[r]);
}

// ---------------- main fused kernel: per (b,t) slice ----------------
__global__ __launch_bounds__(256) void k_main(const float* __restrict__ x,
                                              const float* __restrict__ att,
                                              const float* __restrict__ b_dis)
{
    __shared__ __align__(16) float sx  [SLICE];
    __shared__ __align__(16) float sdis[SLICE];
    __shared__ __align__(16) float sh1s[SLICE];
    __shared__ __align__(16) float sh1c[SLICE];
    __shared__ __align__(16) float sdw [SLICE];
    __shared__ float sS1[NCH], sS2[NCH];
    __shared__ float sred[6*256];

    int bt = blockIdx.x, tid = threadIdx.x;

    const float4* xg = reinterpret_cast<const float4*>(x + (size_t)bt*SLICE);
    for (int p = tid; p < SLICE/4; p += 256)
        reinterpret_cast<float4*>(sx)[p] = __ldg(xg + p);
    __syncthreads();

    if (tid < NCH){
        float s1 = 0.f, s2 = 0.f;
#pragma unroll
        for (int i = 0; i < NND; i++){
            float v = sx[i*NCH + tid];
            s1 += v; s2 += v*v;
        }
        sS1[tid] = s1; sS2[tid] = s2;
    }
    __syncthreads();

    for (int p = tid; p < SLICE; p += 256){
        int c = p & 63;
        float v = sx[p];
        float d = sS2[c] - 2.f*v*sS1[c] + (float)NND*v*v;
        sdis[p] = sqrtf(fmaxf(d, 0.f)) + 1e-8f;
    }
    __syncthreads();

    int o = tid & 63, quad = tid >> 6;
    float h0s[6], h0c[6], tmp[6];

    gemm6(sx,   g_Wt + 0*4096 + o*64, quad, h0s);
    gemm6(sx,   g_Wt + 1*4096 + o*64, quad, tmp);
#pragma unroll
    for (int r = 0; r < 6; r++){ int i = quad + 4*r; if (i < NND) sh1s[i*NCH + o] = tmp[r]; }
    gemm6(sx,   g_Wt + 2*4096 + o*64, quad, h0c);
    gemm6(sx,   g_Wt + 3*4096 + o*64, quad, tmp);
#pragma unroll
    for (int r = 0; r < 6; r++){ int i = quad + 4*r; if (i < NND) sh1c[i*NCH + o] = tmp[r]; }
    gemm6(sdis, g_Wt + 4*4096 + o*64, quad, tmp);
#pragma unroll
    for (int r = 0; r < 6; r++){ int i = quad + 4*r; if (i < NND) sdw[i*NCH + o] = tmp[r]; }
    __syncthreads();

    float ss = 0.f, ssq = 0.f, cs = 0.f, csq = 0.f, zs = 0.f, zsq = 0.f;
    float bo = __ldg(&b_dis[o]);
    size_t obase = (size_t)bt*SLICE + o;

#pragma unroll
    for (int r = 0; r < 6; r++){
        int i = quad + 4*r;
        if (i < NND){
            float vs = h0s[r] * g_diag[0][i*NCH + o];
            int mb = g_rowptr[0][i], me = g_rowptr[0][i+1];
            for (int m = mb; m < me; m++)
                vs += g_offv[0][m*NCH + o] * sh1s[g_offcol[0][m]*NCH + o];

            float vc = h0c[r] * g_diag[1][i*NCH + o];
            mb = g_rowptr[1][i]; me = g_rowptr[1][i+1];
            for (int m = mb; m < me; m++)
                vc += g_offv[1][m*NCH + o] * sh1c[g_offcol[1][m]*NCH + o];

            float vz = bo;
#pragma unroll
            for (int j = 0; j < NND; j++)
                vz += __ldg(&att[i*NND + j]) * sdw[j*NCH + o];

            g_hbuf0[obase + i*NCH] = vs;
            g_hbuf1[obase + i*NCH] = vc;
            g_hbuf2[obase + i*NCH] = vz;

            ss += vs; ssq += vs*vs;
            cs += vc; csq += vc*vc;
            zs += vz; zsq += vz*vz;
        }
    }

    sred[0*256 + tid] = ss;  sred[1*256 + tid] = ssq;
    sred[2*256 + tid] = cs;  sred[3*256 + tid] = csq;
    sred[4*256 + tid] = zs;  sred[5*256 + tid] = zsq;
    __syncthreads();
    // FIX (R1 bug): loop over all 6 stats x 64 channels with 256 threads
    for (int p = tid; p < 384; p += 256){
        int st = p >> 6, oo = p & 63;
        float a = sred[st*256 + oo] + sred[st*256 + 64 + oo]
                + sred[st*256 + 128 + oo] + sred[st*256 + 192 + oo];
        g_part1[(size_t)(st*64 + oo)*NBT + bt] = a;
    }
}

// ---------------- BN stats finalize (deterministic) ----------------
__global__ void k_finalize(int which, const float* __restrict__ gammas,
                           const float* __restrict__ betas)
{
    int ch = blockIdx.x, tid = threadIdx.x;
    int b = ch >> 6, o = ch & 63;
    const float* part = which ? g_part2 : g_part1;
    const float* psum = part + (size_t)((2*b  )*64 + o) * NBT;
    const float* psq  = part + (size_t)((2*b+1)*64 + o) * NBT;
    __shared__ float r1[256], r2[256];
    float s = 0.f, q = 0.f;
    for (int t = tid; t < NBT; t += 256){ s += psum[t]; q += psq[t]; }
    r1[tid] = s; r2[tid] = q;
    __syncthreads();
    for (int off = 128; off; off >>= 1){
        if (tid < off){ r1[tid] += r1[tid+off]; r2[tid] += r2[tid+off]; }
        __syncthreads();
    }
    if (tid == 0){
        const float invM = 1.f / 70400.f;
        float mu  = r1[0]*invM;
        float var = r2[0]*invM - mu*mu;
        int grow = which ? 3 : b;
        float g  = gammas[grow*64 + o], be = betas[grow*64 + o];
        float sc = g * rsqrtf(var + 1e-5f);
        if (which){ g_scale2[o]  = sc; g_shift2[o]  = be - mu*sc; }
        else      { g_scale1[ch] = sc; g_shift1[ch] = be - mu*sc; }
    }
}

// ---------------- BN+ReLU + cat matmul (192 -> 64) + stats ----------------
__global__ __launch_bounds__(256) void k_cat(const float* __restrict__ cat_w)
{
    __shared__ __align__(16) float scat[NND*192];
    __shared__ float sred[2*256];
    int bt = blockIdx.x, tid = threadIdx.x;

    const float* bufs[3] = { g_hbuf0, g_hbuf1, g_hbuf2 };
#pragma unroll
    for (int br = 0; br < 3; br++){
        const float* hb = bufs[br] + (size_t)bt*SLICE;
        for (int p = tid; p < SLICE; p += 256){
            int oo = p & 63, i = p >> 6;
            float sc = g_scale1[br*64 + oo], sh = g_shift1[br*64 + oo];
            float v = fmaxf(hb[p]*sc + sh, 0.f);
            scat[i*192 + br*64 + oo] = v;
        }
    }
    __syncthreads();

    int o = tid & 63, quad = tid >> 6;
    ull acc[6];
#pragma unroll
    for (int r = 0; r < 6; r++) acc[r] = 0ull;
    const ulonglong2* w2 = reinterpret_cast<const ulonglong2*>(cat_w + o*192);
#pragma unroll 4
    for (int cq = 0; cq < 48; cq++){
        ulonglong2 w = __ldg(w2 + cq);
#pragma unroll
        for (int r = 0; r < 6; r++){
            int i = quad + 4*r;
            if (i < NND){
                ulonglong2 xv = *reinterpret_cast<const ulonglong2*>(scat + i*192 + cq*4);
                acc[r] = ffma2(xv.x, w.x, acc[r]);
                acc[r] = ffma2(xv.y, w.y, acc[r]);
            }
        }
    }
    float sum = 0.f, sq = 0.f;
#pragma unroll
    for (int r = 0; r < 6; r++){
        int i = quad + 4*r;
        if (i < NND){
            float v = hsum2(acc[r]);
            g_pre2[(size_t)bt*SLICE + i*NCH + o] = v;
            sum += v; sq += v*v;
        }
    }
    sred[tid] = sum; sred[256 + tid] = sq;
    __syncthreads();
    if (tid < 128){
        int st = tid >> 6, oo = tid & 63;
        float a = sred[st*256 + oo] + sred[st*256 + 64 + oo]
                + sred[st*256 + 128 + oo] + sred[st*256 + 192 + oo];
        g_part2[(size_t)(st*64 + oo)*NBT + bt] = a;
    }
}

// ---------------- final BN+ReLU elementwise ----------------
__global__ void k_out(float* __restrict__ out)
{
    size_t idx = (size_t)blockIdx.x*256 + threadIdx.x;   // float4 index
    if (idx < TOT/4){
        float4 v = reinterpret_cast<const float4*>(g_pre2)[idx];
        int ob = (int)((idx*4) & 63);
        v.x = fmaxf(v.x*g_scale2[ob  ] + g_shift2[ob  ], 0.f);
        v.y = fmaxf(v.y*g_scale2[ob+1] + g_shift2[ob+1], 0.f);
        v.z = fmaxf(v.z*g_scale2[ob+2] + g_shift2[ob+2], 0.f);
        v.w = fmaxf(v.w*g_scale2[ob+3] + g_shift2[ob+3], 0.f);
        reinterpret_cast<float4*>(out)[idx] = v;
    }
}

// ---------------- launch ----------------
extern "C" void kernel_launch(void* const* d_in, const int* in_sizes, int n_in,
                              void* d_out, int out_size)
{
    const float* x        = (const float*)d_in[0];
    const float* W_sym    = (const float*)d_in[1];
    const float* e_sym    = (const float*)d_in[2];
    const float* W_con    = (const float*)d_in[3];
    const float* e_con    = (const float*)d_in[4];
    const float* W_dis    = (const float*)d_in[5];
    const float* att      = (const float*)d_in[6];
    const float* b_dis    = (const float*)d_in[7];
    const float* cat_w    = (const float*)d_in[8];
    const float* gammas   = (const float*)d_in[9];
    const float* betas    = (const float*)d_in[10];
    const int*   rows_sym = (const int*)d_in[11];
    const int*   cols_sym = (const int*)d_in[12];
    const int*   rows_con = (const int*)d_in[13];
    const int*   cols_con = (const int*)d_in[14];
    int nnz_sym = in_sizes[11];
    int nnz_con = in_sizes[13];

    k_prep<<<3, 256>>>(e_sym, rows_sym, cols_sym, nnz_sym,
                       e_con, rows_con, cols_con, nnz_con,
                       W_sym, W_con, W_dis);
    k_main<<<NBT, 256>>>(x, att, b_dis);
    k_finalize<<<192, 256>>>(0, gammas, betas);
    k_cat<<<NBT, 256>>>(cat_w);
    k_finalize<<<64, 256>>>(1, gammas, betas);
    k_out<<<(TOT/4 + 255)/256, 256>>>((float*)d_out);
    (void)n_in; (void)out_size;
}

// round 3
// speedup vs baseline: 1.5056x; 1.5056x over previous
#include <cuda_runtime.h>
#include <cstdint>

typedef unsigned long long ull;

#define NBT   3200          // B*T = 64*50
#define NND   22            // nodes
#define NCH   64            // C = O = 64
#define SLICE (NND*NCH)     // 1408
#define TOT   (NBT*SLICE)   // 4,505,600
#define MAXNZ 484
#define WPAD  68            // padded row stride (floats) for 64-wide weights
#define CPAD  196           // padded row stride for 192-wide cat weights

// ---------------- device scratch (static, no allocs) ----------------
__device__ float g_hbuf0[TOT];
__device__ float g_hbuf1[TOT];
__device__ float g_hbuf2[TOT];
__device__ float g_pre2[TOT];
__device__ float g_part1[6*64*NBT];
__device__ float g_part2[2*64*NBT];
__device__ float g_scale1[192], g_shift1[192];
__device__ float g_scale2[64],  g_shift2[64];
__device__ float g_Wt[5*4096];          // [g][o][c], g: W0s,W1s,W0c,W1c,Wdis
__device__ float g_diag[2][NND*NCH];    // A[o,i,i], stored [i*64+o]
__device__ float g_offv[2][MAXNZ*NCH];  // off-diag values [m*64+o]
__device__ int   g_offcol[2][MAXNZ];
__device__ int   g_rowptr[2][NND+1];

// ---------------- f32x2 helpers ----------------
__device__ __forceinline__ ull ffma2(ull a, ull b, ull c){
    ull d;
    asm("fma.rn.f32x2 %0, %1, %2, %3;" : "=l"(d) : "l"(a), "l"(b), "l"(c));
    return d;
}
__device__ __forceinline__ float hsum2(ull v){
    float a, b;
    asm("mov.b64 {%0, %1}, %2;" : "=f"(a), "=f"(b) : "l"(v));
    return a + b;
}

// ---------------- prep: softmax adjacencies (sparse) + weight transpose ----------------
__global__ void k_prep(const float* __restrict__ e_sym, const int* __restrict__ rows_sym,
                       const int* __restrict__ cols_sym, int nnz_sym,
                       const float* __restrict__ e_con, const int* __restrict__ rows_con,
                       const int* __restrict__ cols_con, int nnz_con,
                       const float* __restrict__ W_sym, const float* __restrict__ W_con,
                       const float* __restrict__ W_dis)
{
    int blk = blockIdx.x, tid = threadIdx.x;
    if (blk == 2){
        // transpose 5 (64,64) weight matrices to [o][c]
        for (int p = tid; p < 5*4096; p += 256){
            int g = p >> 12, rem = p & 4095, c = rem >> 6, o = rem & 63;
            float v;
            if (g < 2)      v = W_sym[g*4096 + c*64 + o];
            else if (g < 4) v = W_con[(g-2)*4096 + c*64 + o];
            else            v = W_dis[c*64 + o];
            g_Wt[g*4096 + o*64 + c] = v;
        }
        return;
    }
    int br = blk;
    const float* e   = br ? e_con   : e_sym;
    const int* rows  = br ? rows_con : rows_sym;
    const int* cols  = br ? cols_con : cols_sym;
    int nnz          = br ? nnz_con : nnz_sym;

    __shared__ float sden[NND*NCH];
    __shared__ int   smap[512];

    for (int p = tid; p < NND*NCH; p += 256) g_diag[br][p] = 0.f;
    __syncthreads();

    if (tid == 0){
        int m = 0;
        for (int k = 0; k < nnz; k++){
            int r = rows[k], c = cols[k];
            if (c != r){ smap[k] = m; g_offcol[br][m] = c; m++; }
            else smap[k] = -1;
        }
        for (int i = 0; i <= NND; i++){
            int cnt = 0;
            for (int k = 0; k < nnz; k++)
                if (cols[k] != rows[k] && rows[k] < i) cnt++;
            g_rowptr[br][i] = cnt;
        }
    }
    __syncthreads();

    // softmax denominators per (row i, channel o)
    for (int p = tid; p < NND*NCH; p += 256){
        int i = p >> 6, o = p & 63;
        float s = 0.f;
        for (int k = 0; k < nnz; k++)
            if (rows[k] == i) s += expf(e[o*nnz + k]);
        sden[p] = s;
    }
    __syncthreads();

    for (int p = tid; p < 64*nnz; p += 256){
        int k = p >> 6, o = p & 63;
        int r = rows[k];
        float v = expf(e[o*nnz + k]) / sden[r*64 + o];
        int m = smap[k];
        if (m < 0) g_diag[br][r*64 + o] = v;
        else       g_offv[br][m*64 + o] = v;
    }
}

// ---------------- small GEMM from smem padded weights ----------------
// src: 22x64 activation (rows 64 floats, warp-uniform -> broadcast LDS)
// swrow: this thread's padded weight row in smem (stride WPAD, conflict-free LDS.128)
__device__ __forceinline__ void gemm6p(const float* __restrict__ src,
                                       const float* __restrict__ swrow,
                                       int quad, float out[6])
{
    ull acc[6];
#pragma unroll
    for (int r = 0; r < 6; r++) acc[r] = 0ull;
    const ulonglong2* w2 = reinterpret_cast<const ulonglong2*>(swrow);
#pragma unroll
    for (int cq = 0; cq < 16; cq++){
        ulonglong2 w = w2[cq];
#pragma unroll
        for (int r = 0; r < 6; r++){
            int i = quad + 4*r;
            if (i < NND){
                ulonglong2 xv = *reinterpret_cast<const ulonglong2*>(src + i*NCH + cq*4);
                acc[r] = ffma2(xv.x, w.x, acc[r]);
                acc[r] = ffma2(xv.y, w.y, acc[r]);
            }
        }
    }
#pragma unroll
    for (int r = 0; r < 6; r++) out[r] = hsum2(acc[r]);
}

__device__ __forceinline__ void stage_w(float* sw, const float* __restrict__ gsrc, int tid){
    for (int p = tid; p < 4096; p += 256)
        sw[(p >> 6)*WPAD + (p & 63)] = gsrc[p];
}

// ---------------- main fused kernel: per (b,t) slice ----------------
__global__ __launch_bounds__(256) void k_main(const float* __restrict__ x,
                                              const float* __restrict__ att,
                                              const float* __restrict__ b_dis)
{
    __shared__ __align__(16) float sx  [SLICE];
    __shared__ __align__(16) float sA  [SLICE];   // sdis, then reused as sh1s
    __shared__ __align__(16) float sh1c[SLICE];
    __shared__ __align__(16) float sdw [SLICE];
    __shared__ __align__(16) float sw  [64*WPAD]; // padded weight staging
    __shared__ float satt[NND*NND];
    __shared__ float sS1[NCH], sS2[NCH];
    __shared__ float sred[6*256];

    int bt = blockIdx.x, tid = threadIdx.x;

    const float4* xg = reinterpret_cast<const float4*>(x + (size_t)bt*SLICE);
    for (int p = tid; p < SLICE/4; p += 256)
        reinterpret_cast<float4*>(sx)[p] = __ldg(xg + p);
    for (int p = tid; p < NND*NND; p += 256) satt[p] = __ldg(&att[p]);
    __syncthreads();

    if (tid < NCH){
        float s1 = 0.f, s2 = 0.f;
#pragma unroll
        for (int i = 0; i < NND; i++){
            float v = sx[i*NCH + tid];
            s1 += v; s2 += v*v;
        }
        sS1[tid] = s1; sS2[tid] = s2;
    }
    __syncthreads();

    for (int p = tid; p < SLICE; p += 256){
        int c = p & 63;
        float v = sx[p];
        float d = sS2[c] - 2.f*v*sS1[c] + (float)NND*v*v;
        sA[p] = sqrtf(fmaxf(d, 0.f)) + 1e-8f;     // dis
    }
    // stage Wdis while dis is being computed (different smem)
    stage_w(sw, g_Wt + 4*4096, tid);
    __syncthreads();

    int o = tid & 63, quad = tid >> 6;
    float h0s[6], h0c[6], tmp[6];
    const float* swrow = sw + o*WPAD;

    // gemm: dis @ Wdis -> sdw
    gemm6p(sA, swrow, quad, tmp);
#pragma unroll
    for (int r = 0; r < 6; r++){ int i = quad + 4*r; if (i < NND) sdw[i*NCH + o] = tmp[r]; }
    __syncthreads();

    // gemm: x @ W1s -> sA (dis no longer needed)
    stage_w(sw, g_Wt + 1*4096, tid);
    __syncthreads();
    gemm6p(sx, swrow, quad, tmp);
#pragma unroll
    for (int r = 0; r < 6; r++){ int i = quad + 4*r; if (i < NND) sA[i*NCH + o] = tmp[r]; }
    __syncthreads();

    // gemm: x @ W1c -> sh1c
    stage_w(sw, g_Wt + 3*4096, tid);
    __syncthreads();
    gemm6p(sx, swrow, quad, tmp);
#pragma unroll
    for (int r = 0; r < 6; r++){ int i = quad + 4*r; if (i < NND) sh1c[i*NCH + o] = tmp[r]; }
    __syncthreads();

    // gemm: x @ W0s -> regs
    stage_w(sw, g_Wt + 0*4096, tid);
    __syncthreads();
    gemm6p(sx, swrow, quad, h0s);
    __syncthreads();

    // gemm: x @ W0c -> regs
    stage_w(sw, g_Wt + 2*4096, tid);
    __syncthreads();
    gemm6p(sx, swrow, quad, h0c);

    float ss = 0.f, ssq = 0.f, cs = 0.f, csq = 0.f, zs = 0.f, zsq = 0.f;
    float bo = __ldg(&b_dis[o]);
    size_t obase = (size_t)bt*SLICE + o;

#pragma unroll
    for (int r = 0; r < 6; r++){
        int i = quad + 4*r;
        if (i < NND){
            float vs = h0s[r] * g_diag[0][i*NCH + o];
            int mb = g_rowptr[0][i], me = g_rowptr[0][i+1];
            for (int m = mb; m < me; m++)
                vs += g_offv[0][m*NCH + o] * sA[g_offcol[0][m]*NCH + o];

            float vc = h0c[r] * g_diag[1][i*NCH + o];
            mb = g_rowptr[1][i]; me = g_rowptr[1][i+1];
            for (int m = mb; m < me; m++)
                vc += g_offv[1][m*NCH + o] * sh1c[g_offcol[1][m]*NCH + o];

            float vz = bo;
#pragma unroll
            for (int j = 0; j < NND; j++)
                vz += satt[i*NND + j] * sdw[j*NCH + o];

            g_hbuf0[obase + i*NCH] = vs;
            g_hbuf1[obase + i*NCH] = vc;
            g_hbuf2[obase + i*NCH] = vz;

            ss += vs; ssq += vs*vs;
            cs += vc; csq += vc*vc;
            zs += vz; zsq += vz*vz;
        }
    }

    sred[0*256 + tid] = ss;  sred[1*256 + tid] = ssq;
    sred[2*256 + tid] = cs;  sred[3*256 + tid] = csq;
    sred[4*256 + tid] = zs;  sred[5*256 + tid] = zsq;
    __syncthreads();
    for (int p = tid; p < 384; p += 256){
        int st = p >> 6, oo = p & 63;
        float a = sred[st*256 + oo] + sred[st*256 + 64 + oo]
                + sred[st*256 + 128 + oo] + sred[st*256 + 192 + oo];
        g_part1[(size_t)(st*64 + oo)*NBT + bt] = a;
    }
}

// ---------------- BN stats finalize (deterministic) ----------------
__global__ void k_finalize(int which, const float* __restrict__ gammas,
                           const float* __restrict__ betas)
{
    int ch = blockIdx.x, tid = threadIdx.x;
    int b = ch >> 6, o = ch & 63;
    const float* part = which ? g_part2 : g_part1;
    const float* psum = part + (size_t)((2*b  )*64 + o) * NBT;
    const float* psq  = part + (size_t)((2*b+1)*64 + o) * NBT;
    __shared__ float r1[256], r2[256];
    float s = 0.f, q = 0.f;
    for (int t = tid; t < NBT; t += 256){ s += psum[t]; q += psq[t]; }
    r1[tid] = s; r2[tid] = q;
    __syncthreads();
    for (int off = 128; off; off >>= 1){
        if (tid < off){ r1[tid] += r1[tid+off]; r2[tid] += r2[tid+off]; }
        __syncthreads();
    }
    if (tid == 0){
        const float invM = 1.f / 70400.f;
        float mu  = r1[0]*invM;
        float var = r2[0]*invM - mu*mu;
        int grow = which ? 3 : b;
        float g  = gammas[grow*64 + o], be = betas[grow*64 + o];
        float sc = g * rsqrtf(var + 1e-5f);
        if (which){ g_scale2[o]  = sc; g_shift2[o]  = be - mu*sc; }
        else      { g_scale1[ch] = sc; g_shift1[ch] = be - mu*sc; }
    }
}

// ---------------- BN+ReLU + cat matmul (192 -> 64) + stats ----------------
__global__ __launch_bounds__(256) void k_cat(const float* __restrict__ cat_w)
{
    __shared__ __align__(16) float scat[NND*192];
    __shared__ __align__(16) float swc [64*CPAD];  // padded cat weights
    __shared__ float sred[2*256];
    int bt = blockIdx.x, tid = threadIdx.x;

    // stage cat_w with padding (layout already [o][f])
    for (int p = tid; p < 64*192; p += 256)
        swc[(p / 192)*CPAD + (p % 192)] = __ldg(&cat_w[p]);

    const float* bufs[3] = { g_hbuf0, g_hbuf1, g_hbuf2 };
#pragma unroll
    for (int br = 0; br < 3; br++){
        const float* hb = bufs[br] + (size_t)bt*SLICE;
        for (int p = tid; p < SLICE; p += 256){
            int oo = p & 63, i = p >> 6;
            float sc = g_scale1[br*64 + oo], sh = g_shift1[br*64 + oo];
            float v = fmaxf(hb[p]*sc + sh, 0.f);
            scat[i*192 + br*64 + oo] = v;
        }
    }
    __syncthreads();

    int o = tid & 63, quad = tid >> 6;
    ull acc[6];
#pragma unroll
    for (int r = 0; r < 6; r++) acc[r] = 0ull;
    const ulonglong2* w2 = reinterpret_cast<const ulonglong2*>(swc + o*CPAD);
#pragma unroll 6
    for (int cq = 0; cq < 48; cq++){
        ulonglong2 w = w2[cq];
#pragma unroll
        for (int r = 0; r < 6; r++){
            int i = quad + 4*r;
            if (i < NND){
                ulonglong2 xv = *reinterpret_cast<const ulonglong2*>(scat + i*192 + cq*4);
                acc[r] = ffma2(xv.x, w.x, acc[r]);
                acc[r] = ffma2(xv.y, w.y, acc[r]);
            }
        }
    }
    float sum = 0.f, sq = 0.f;
#pragma unroll
    for (int r = 0; r < 6; r++){
        int i = quad + 4*r;
        if (i < NND){
            float v = hsum2(acc[r]);
            g_pre2[(size_t)bt*SLICE + i*NCH + o] = v;
            sum += v; sq += v*v;
        }
    }
    sred[tid] = sum; sred[256 + tid] = sq;
    __syncthreads();
    if (tid < 128){
        int st = tid >> 6, oo = tid & 63;
        float a = sred[st*256 + oo] + sred[st*256 + 64 + oo]
                + sred[st*256 + 128 + oo] + sred[st*256 + 192 + oo];
        g_part2[(size_t)(st*64 + oo)*NBT + bt] = a;
    }
}

// ---------------- final BN+ReLU elementwise ----------------
__global__ void k_out(float* __restrict__ out)
{
    size_t idx = (size_t)blockIdx.x*256 + threadIdx.x;   // float4 index
    if (idx < TOT/4){
        float4 v = reinterpret_cast<const float4*>(g_pre2)[idx];
        int ob = (int)((idx*4) & 63);
        v.x = fmaxf(v.x*g_scale2[ob  ] + g_shift2[ob  ], 0.f);
        v.y = fmaxf(v.y*g_scale2[ob+1] + g_shift2[ob+1], 0.f);
        v.z = fmaxf(v.z*g_scale2[ob+2] + g_shift2[ob+2], 0.f);
        v.w = fmaxf(v.w*g_scale2[ob+3] + g_shift2[ob+3], 0.f);
        reinterpret_cast<float4*>(out)[idx] = v;
    }
}

// ---------------- launch ----------------
extern "C" void kernel_launch(void* const* d_in, const int* in_sizes, int n_in,
                              void* d_out, int out_size)
{
    const float* x        = (const float*)d_in[0];
    const float* W_sym    = (const float*)d_in[1];
    const float* e_sym    = (const float*)d_in[2];
    const float* W_con    = (const float*)d_in[3];
    const float* e_con    = (const float*)d_in[4];
    const float* W_dis    = (const float*)d_in[5];
    const float* att      = (const float*)d_in[6];
    const float* b_dis    = (const float*)d_in[7];
    const float* cat_w    = (const float*)d_in[8];
    const float* gammas   = (const float*)d_in[9];
    const float* betas    = (const float*)d_in[10];
    const int*   rows_sym = (const int*)d_in[11];
    const int*   cols_sym = (const int*)d_in[12];
    const int*   rows_con = (const int*)d_in[13];
    const int*   cols_con = (const int*)d_in[14];
    int nnz_sym = in_sizes[11];
    int nnz_con = in_sizes[13];

    k_prep<<<3, 256>>>(e_sym, rows_sym, cols_sym, nnz_sym,
                       e_con, rows_con, cols_con, nnz_con,
                       W_sym, W_con, W_dis);
    k_main<<<NBT, 256>>>(x, att, b_dis);
    k_finalize<<<192, 256>>>(0, gammas, betas);
    k_cat<<<NBT, 256>>>(cat_w);
    k_finalize<<<64, 256>>>(1, gammas, betas);
    k_out<<<(TOT/4 + 255)/256, 256>>>((float*)d_out);
    (void)n_in; (void)out_size;
}

// round 4
// speedup vs baseline: 2.1935x; 1.4569x over previous
#include <cuda_runtime.h>
#include <cstdint>

typedef unsigned int uint32;

#define NBT   3200          // B*T
#define NND   22
#define NCH   64
#define SLICE (NND*NCH)     // 1408
#define TOT   (NBT*SLICE)
#define MAXNZ 484
#define SPB   4             // slices per block
#define GRID1 (NBT/SPB)     // 800

// ---------------- device scratch ----------------
__device__ float g_hbuf0[TOT];
__device__ float g_hbuf1[TOT];
__device__ float g_hbuf2[TOT];
__device__ float g_pre2[TOT];
__device__ float g_part1[6*64*NBT];
__device__ float g_part2[2*64*NBT];
__device__ float g_scale1[192], g_shift1[192];
__device__ float g_scale2[64],  g_shift2[64];
__device__ float g_Wt[5*4096];          // [g][o][c]
__device__ float g_diag[2][NND*NCH];
__device__ float g_offv[2][MAXNZ*NCH];
__device__ int   g_offcol[2][MAXNZ];
__device__ int   g_rowptr[2][NND+1];

// ---------------- helpers ----------------
__device__ __forceinline__ uint32 tf32(float f){
    uint32 r; asm("cvt.rna.tf32.f32 %0, %1;" : "=r"(r) : "f"(f)); return r;
}
__device__ __forceinline__ void mma_tf32(float c[4], const uint32 a[4], const uint32 b[2]){
    asm volatile("mma.sync.aligned.m16n8k8.row.col.f32.tf32.tf32.f32 "
                 "{%0,%1,%2,%3}, {%4,%5,%6,%7}, {%8,%9}, {%0,%1,%2,%3};"
                 : "+f"(c[0]), "+f"(c[1]), "+f"(c[2]), "+f"(c[3])
                 : "r"(a[0]), "r"(a[1]), "r"(a[2]), "r"(a[3]),
                   "r"(b[0]), "r"(b[1]));
}
__device__ __forceinline__ float redg(float v){  // sum lanes {l, l+4, ..., l+28}
    v += __shfl_down_sync(0xffffffffu, v, 16);
    v += __shfl_down_sync(0xffffffffu, v, 8);
    v += __shfl_down_sync(0xffffffffu, v, 4);
    return v;
}

// ---------------- prep (unchanged, proven) ----------------
__global__ void k_prep(const float* __restrict__ e_sym, const int* __restrict__ rows_sym,
                       const int* __restrict__ cols_sym, int nnz_sym,
                       const float* __restrict__ e_con, const int* __restrict__ rows_con,
                       const int* __restrict__ cols_con, int nnz_con,
                       const float* __restrict__ W_sym, const float* __restrict__ W_con,
                       const float* __restrict__ W_dis)
{
    int blk = blockIdx.x, tid = threadIdx.x;
    if (blk == 2){
        for (int p = tid; p < 5*4096; p += 256){
            int g = p >> 12, rem = p & 4095, c = rem >> 6, o = rem & 63;
            float v;
            if (g < 2)      v = W_sym[g*4096 + c*64 + o];
            else if (g < 4) v = W_con[(g-2)*4096 + c*64 + o];
            else            v = W_dis[c*64 + o];
            g_Wt[g*4096 + o*64 + c] = v;
        }
        return;
    }
    int br = blk;
    const float* e  = br ? e_con   : e_sym;
    const int* rows = br ? rows_con : rows_sym;
    const int* cols = br ? cols_con : cols_sym;
    int nnz         = br ? nnz_con : nnz_sym;

    __shared__ float sden[NND*NCH];
    __shared__ int   smap[512];

    for (int p = tid; p < NND*NCH; p += 256) g_diag[br][p] = 0.f;
    __syncthreads();

    if (tid == 0){
        int m = 0;
        for (int k = 0; k < nnz; k++){
            int r = rows[k], c = cols[k];
            if (c != r){ smap[k] = m; g_offcol[br][m] = c; m++; }
            else smap[k] = -1;
        }
        for (int i = 0; i <= NND; i++){
            int cnt = 0;
            for (int k = 0; k < nnz; k++)
                if (cols[k] != rows[k] && rows[k] < i) cnt++;
            g_rowptr[br][i] = cnt;
        }
    }
    __syncthreads();

    for (int p = tid; p < NND*NCH; p += 256){
        int i = p >> 6, o = p & 63;
        float s = 0.f;
        for (int k = 0; k < nnz; k++)
            if (rows[k] == i) s += expf(e[o*nnz + k]);
        sden[p] = s;
    }
    __syncthreads();

    for (int p = tid; p < 64*nnz; p += 256){
        int k = p >> 6, o = p & 63;
        int r = rows[k];
        float v = expf(e[o*nnz + k]) / sden[r*64 + o];
        int m = smap[k];
        if (m < 0) g_diag[br][r*64 + o] = v;
        else       g_offv[br][m*64 + o] = v;
    }
}

// A-fragment gemm over K=64 from padded fp32 smem buffer (pitch 68)
__device__ __forceinline__ void mma8(const float* __restrict__ sbuf,
                                     const uint32 (&bwk)[8][2],
                                     int g, int tig, float acc0[4], float acc1[4]){
    int r2ok = (g + 16) < NND;
#pragma unroll
    for (int k8 = 0; k8 < 8; k8++){
        int c0 = k8*8 + tig, c1 = c0 + 4;
        uint32 a0[4], a1[4];
        a0[0] = tf32(sbuf[ g      *68 + c0]);
        a0[1] = tf32(sbuf[(g + 8) *68 + c0]);
        a0[2] = tf32(sbuf[ g      *68 + c1]);
        a0[3] = tf32(sbuf[(g + 8) *68 + c1]);
        a1[0] = r2ok ? tf32(sbuf[(g + 16)*68 + c0]) : 0u;
        a1[1] = 0u;
        a1[2] = r2ok ? tf32(sbuf[(g + 16)*68 + c1]) : 0u;
        a1[3] = 0u;
        mma_tf32(acc0, a0, bwk[k8]);
        mma_tf32(acc1, a1, bwk[k8]);
    }
}

// ---------------- main fused kernel: 4 slices per block ----------------
__global__ __launch_bounds__(256) void k_main(const float* __restrict__ x,
                                              const float* __restrict__ att,
                                              const float* __restrict__ b_dis)
{
    __shared__ __align__(16) float sx  [NND*68];
    __shared__ __align__(16) float sdis[NND*68];
    __shared__ float  sh1 [NND*64];
    __shared__ uint32 sdwT[64*28];
    __shared__ float  satt[NND*NND];
    __shared__ float  sdiag[2][NND*64];
    __shared__ int    srp[2][NND+1];
    __shared__ int    socol[2][MAXNZ];
    __shared__ float  sS1[64], sS2[64];

    int tid = threadIdx.x;
    int lane = tid & 31, w = tid >> 5;
    int g = lane >> 2, tig = lane & 3;
    int n0 = w*8;
    int o0 = n0 + 2*tig;
    int r2ok = (g + 16) < NND;

    // persistent B fragments (all 5 weight matrices), warp-exclusive ntile
    uint32 bw[5][8][2];
#pragma unroll
    for (int gm = 0; gm < 5; gm++)
#pragma unroll
        for (int k8 = 0; k8 < 8; k8++){
            const float* wp = g_Wt + gm*4096 + (n0 + g)*64 + k8*8 + tig;
            bw[gm][k8][0] = tf32(__ldg(wp));
            bw[gm][k8][1] = tf32(__ldg(wp + 4));
        }

    // block-constant staging
    for (int p = tid; p < NND*NND; p += 256) satt[p] = __ldg(&att[p]);
    for (int p = tid; p < 2*NND*64; p += 256){
        int b = p / (NND*64), r = p % (NND*64);
        sdiag[b][r] = g_diag[b][r];
    }
    for (int p = tid; p < 2*(NND+1); p += 256) srp[p/(NND+1)][p%(NND+1)] = g_rowptr[p/(NND+1)][p%(NND+1)];
    for (int p = tid; p < 2*MAXNZ; p += 256) socol[p/MAXNZ][p%MAXNZ] = g_offcol[p/MAXNZ][p%MAXNZ];

    float2 bd = *(const float2*)&b_dis[o0];

    for (int s = 0; s < SPB; s++){
        int bt = blockIdx.x*SPB + s;
        __syncthreads();   // previous slice fully consumed

        // stage x (padded pitch 68)
        const float4* xg = (const float4*)(x + (size_t)bt*SLICE);
        for (int p = tid; p < SLICE/4; p += 256){
            float4 v = __ldg(xg + p);
            int i = p >> 4, c = (p & 15)*4;
            *(float4*)&sx[i*68 + c] = v;
        }
        __syncthreads();

        if (tid < 64){
            float s1 = 0.f, s2 = 0.f;
#pragma unroll
            for (int i = 0; i < NND; i++){
                float v = sx[i*68 + tid];
                s1 += v; s2 += v*v;
            }
            sS1[tid] = s1; sS2[tid] = s2;
        }
        __syncthreads();

        for (int p = tid; p < SLICE; p += 256){
            int i = p >> 6, c = p & 63;
            float v = sx[i*68 + c];
            float d = sS2[c] - 2.f*v*sS1[c] + (float)NND*v*v;
            sdis[i*68 + c] = sqrtf(fmaxf(d, 0.f)) + 1e-8f;
        }
        __syncthreads();

        size_t obase = (size_t)bt*SLICE;

        // ===== branches s (br=0) and c (br=1) =====
#pragma unroll
        for (int br = 0; br < 2; br++){
            // h1 gemm -> sh1 (warp-exclusive column stripe)
            float acc0[4] = {0,0,0,0}, acc1[4] = {0,0,0,0};
            mma8(sx, bw[2*br + 1], g, tig, acc0, acc1);
            sh1[ g      *64 + o0    ] = acc0[0];
            sh1[ g      *64 + o0 + 1] = acc0[1];
            sh1[(g + 8) *64 + o0    ] = acc0[2];
            sh1[(g + 8) *64 + o0 + 1] = acc0[3];
            if (r2ok){
                sh1[(g + 16)*64 + o0    ] = acc1[0];
                sh1[(g + 16)*64 + o0 + 1] = acc1[1];
            }
            __syncwarp();

            // h0 gemm
            float h0a[4] = {0,0,0,0}, h0b[4] = {0,0,0,0};
            mma8(sx, bw[2*br], g, tig, h0a, h0b);

            // mix epilogue
            float su0 = 0.f, su1 = 0.f, sq0 = 0.f, sq1 = 0.f;
            int rr[3] = { g, g + 8, g + 16 };
            float va[3] = { h0a[0], h0a[2], h0b[0] };
            float vb[3] = { h0a[1], h0a[3], h0b[1] };
#pragma unroll
            for (int q = 0; q < 3; q++){
                if (q == 2 && !r2ok) break;
                int r = rr[q];
                float2 dg = *(const float2*)&sdiag[br][r*64 + o0];
                float v0 = va[q]*dg.x, v1 = vb[q]*dg.y;
                int mb = srp[br][r], me = srp[br][r+1];
                for (int m = mb; m < me; m++){
                    int cm = socol[br][m];
                    float2 ov = *(const float2*)&g_offv[br][m*64 + o0];
                    v0 += ov.x * sh1[cm*64 + o0];
                    v1 += ov.y * sh1[cm*64 + o0 + 1];
                }
                float2 st = make_float2(v0, v1);
                if (br == 0) *(float2*)&g_hbuf0[obase + r*64 + o0] = st;
                else         *(float2*)&g_hbuf1[obase + r*64 + o0] = st;
                su0 += v0; su1 += v1; sq0 += v0*v0; sq1 += v1*v1;
            }
            su0 = redg(su0); su1 = redg(su1); sq0 = redg(sq0); sq1 = redg(sq1);
            if (lane < 4){
                g_part1[(size_t)((2*br  )*64 + o0    )*NBT + bt] = su0;
                g_part1[(size_t)((2*br  )*64 + o0 + 1)*NBT + bt] = su1;
                g_part1[(size_t)((2*br+1)*64 + o0    )*NBT + bt] = sq0;
                g_part1[(size_t)((2*br+1)*64 + o0 + 1)*NBT + bt] = sq1;
            }
            __syncwarp();
        }

        // ===== z branch: dis @ Wdis, then att @ (that) =====
        {
            float acc0[4] = {0,0,0,0}, acc1[4] = {0,0,0,0};
            mma8(sdis, bw[4], g, tig, acc0, acc1);
            // store transposed tf32 for z-mma B
            sdwT[ o0     *28 + g     ] = tf32(acc0[0]);
            sdwT[(o0 + 1)*28 + g     ] = tf32(acc0[1]);
            sdwT[ o0     *28 + g + 8 ] = tf32(acc0[2]);
            sdwT[(o0 + 1)*28 + g + 8 ] = tf32(acc0[3]);
            if (r2ok){
                sdwT[ o0     *28 + g + 16] = tf32(acc1[0]);
                sdwT[(o0 + 1)*28 + g + 16] = tf32(acc1[1]);
            }
            __syncwarp();

            float az0[4] = {0,0,0,0}, az1[4] = {0,0,0,0};
#pragma unroll
            for (int k8 = 0; k8 < 3; k8++){
                int c0 = k8*8 + tig, c1 = c0 + 4;
                uint32 a0[4], a1[4], bz[2];
                a0[0] = (c0 < NND) ? tf32(satt[ g      *NND + c0]) : 0u;
                a0[1] = (c0 < NND) ? tf32(satt[(g + 8) *NND + c0]) : 0u;
                a0[2] = (c1 < NND) ? tf32(satt[ g      *NND + c1]) : 0u;
                a0[3] = (c1 < NND) ? tf32(satt[(g + 8) *NND + c1]) : 0u;
                a1[0] = (r2ok && c0 < NND) ? tf32(satt[(g + 16)*NND + c0]) : 0u;
                a1[1] = 0u;
                a1[2] = (r2ok && c1 < NND) ? tf32(satt[(g + 16)*NND + c1]) : 0u;
                a1[3] = 0u;
                bz[0] = (c0 < NND) ? sdwT[(n0 + g)*28 + c0] : 0u;
                bz[1] = (c1 < NND) ? sdwT[(n0 + g)*28 + c1] : 0u;
                mma_tf32(az0, a0, bz);
                mma_tf32(az1, a1, bz);
            }
            float su0 = 0.f, su1 = 0.f, sq0 = 0.f, sq1 = 0.f;
            int rr[3] = { g, g + 8, g + 16 };
            float va[3] = { az0[0], az0[2], az1[0] };
            float vb[3] = { az0[1], az0[3], az1[1] };
#pragma unroll
            for (int q = 0; q < 3; q++){
                if (q == 2 && !r2ok) break;
                int r = rr[q];
                float v0 = va[q] + bd.x, v1 = vb[q] + bd.y;
                *(float2*)&g_hbuf2[obase + r*64 + o0] = make_float2(v0, v1);
                su0 += v0; su1 += v1; sq0 += v0*v0; sq1 += v1*v1;
            }
            su0 = redg(su0); su1 = redg(su1); sq0 = redg(sq0); sq1 = redg(sq1);
            if (lane < 4){
                g_part1[(size_t)(4*64 + o0    )*NBT + bt] = su0;
                g_part1[(size_t)(4*64 + o0 + 1)*NBT + bt] = su1;
                g_part1[(size_t)(5*64 + o0    )*NBT + bt] = sq0;
                g_part1[(size_t)(5*64 + o0 + 1)*NBT + bt] = sq1;
            }
        }
    }
}

// ---------------- BN stats finalize (unchanged) ----------------
__global__ void k_finalize(int which, const float* __restrict__ gammas,
                           const float* __restrict__ betas)
{
    int ch = blockIdx.x, tid = threadIdx.x;
    int b = ch >> 6, o = ch & 63;
    const float* part = which ? g_part2 : g_part1;
    const float* psum = part + (size_t)((2*b  )*64 + o) * NBT;
    const float* psq  = part + (size_t)((2*b+1)*64 + o) * NBT;
    __shared__ float r1[256], r2[256];
    float s = 0.f, q = 0.f;
    for (int t = tid; t < NBT; t += 256){ s += psum[t]; q += psq[t]; }
    r1[tid] = s; r2[tid] = q;
    __syncthreads();
    for (int off = 128; off; off >>= 1){
        if (tid < off){ r1[tid] += r1[tid+off]; r2[tid] += r2[tid+off]; }
        __syncthreads();
    }
    if (tid == 0){
        const float invM = 1.f / 70400.f;
        float mu  = r1[0]*invM;
        float var = r2[0]*invM - mu*mu;
        int grow = which ? 3 : b;
        float g  = gammas[grow*64 + o], be = betas[grow*64 + o];
        float sc = g * rsqrtf(var + 1e-5f);
        if (which){ g_scale2[o]  = sc; g_shift2[o]  = be - mu*sc; }
        else      { g_scale1[ch] = sc; g_shift1[ch] = be - mu*sc; }
    }
}

// ---------------- BN+ReLU + cat matmul (192->64) + stats ----------------
__global__ __launch_bounds__(256) void k_cat(const float* __restrict__ cat_w)
{
    __shared__ __align__(16) float scat[NND*196];
    __shared__ float ssc[192], ssh[192];

    int tid = threadIdx.x;
    int lane = tid & 31, w = tid >> 5;
    int g = lane >> 2, tig = lane & 3;
    int n0 = w*8;
    int o0 = n0 + 2*tig;
    int r2ok = (g + 16) < NND;

    // persistent B fragments: 24 ksteps x 2
    uint32 bc[24][2];
#pragma unroll
    for (int k8 = 0; k8 < 24; k8++){
        const float* wp = cat_w + (n0 + g)*192 + k8*8 + tig;
        bc[k8][0] = tf32(__ldg(wp));
        bc[k8][1] = tf32(__ldg(wp + 4));
    }
    for (int p = tid; p < 192; p += 256){ ssc[p] = g_scale1[p]; ssh[p] = g_shift1[p]; }

    for (int s = 0; s < SPB; s++){
        int bt = blockIdx.x*SPB + s;
        __syncthreads();

        // stage BN(ReLU(hbuf)) into scat (pitch 196)
        const float* bufs[3] = { g_hbuf0, g_hbuf1, g_hbuf2 };
#pragma unroll
        for (int br = 0; br < 3; br++){
            const float* hb = bufs[br] + (size_t)bt*SLICE;
            for (int p = tid; p < SLICE; p += 256){
                int oo = p & 63, i = p >> 6;
                float v = fmaxf(hb[p]*ssc[br*64 + oo] + ssh[br*64 + oo], 0.f);
                scat[i*196 + br*64 + oo] = v;
            }
        }
        __syncthreads();

        float acc0[4] = {0,0,0,0}, acc1[4] = {0,0,0,0};
#pragma unroll
        for (int k8 = 0; k8 < 24; k8++){
            int c0 = k8*8 + tig, c1 = c0 + 4;
            uint32 a0[4], a1[4];
            a0[0] = tf32(scat[ g      *196 + c0]);
            a0[1] = tf32(scat[(g + 8) *196 + c0]);
            a0[2] = tf32(scat[ g      *196 + c1]);
            a0[3] = tf32(scat[(g + 8) *196 + c1]);
            a1[0] = r2ok ? tf32(scat[(g + 16)*196 + c0]) : 0u;
            a1[1] = 0u;
            a1[2] = r2ok ? tf32(scat[(g + 16)*196 + c1]) : 0u;
            a1[3] = 0u;
            mma_tf32(acc0, a0, bc[k8]);
            mma_tf32(acc1, a1, bc[k8]);
        }

        float su0 = 0.f, su1 = 0.f, sq0 = 0.f, sq1 = 0.f;
        int rr[3] = { g, g + 8, g + 16 };
        float va[3] = { acc0[0], acc0[2], acc1[0] };
        float vb[3] = { acc0[1], acc0[3], acc1[1] };
        size_t obase = (size_t)bt*SLICE;
#pragma unroll
        for (int q = 0; q < 3; q++){
            if (q == 2 && !r2ok) break;
            int r = rr[q];
            float v0 = va[q], v1 = vb[q];
            *(float2*)&g_pre2[obase + r*64 + o0] = make_float2(v0, v1);
            su0 += v0; su1 += v1; sq0 += v0*v0; sq1 += v1*v1;
        }
        su0 = redg(su0); su1 = redg(su1); sq0 = redg(sq0); sq1 = redg(sq1);
        if (lane < 4){
            g_part2[(size_t)(o0     )*NBT + bt] = su0;
            g_part2[(size_t)(o0 + 1 )*NBT + bt] = su1;
            g_part2[(size_t)(64 + o0    )*NBT + bt] = sq0;
            g_part2[(size_t)(64 + o0 + 1)*NBT + bt] = sq1;
        }
    }
}

// ---------------- final BN+ReLU elementwise ----------------
__global__ void k_out(float* __restrict__ out)
{
    size_t idx = (size_t)blockIdx.x*256 + threadIdx.x;
    if (idx < TOT/4){
        float4 v = reinterpret_cast<const float4*>(g_pre2)[idx];
        int ob = (int)((idx*4) & 63);
        v.x = fmaxf(v.x*g_scale2[ob  ] + g_shift2[ob  ], 0.f);
        v.y = fmaxf(v.y*g_scale2[ob+1] + g_shift2[ob+1], 0.f);
        v.z = fmaxf(v.z*g_scale2[ob+2] + g_shift2[ob+2], 0.f);
        v.w = fmaxf(v.w*g_scale2[ob+3] + g_shift2[ob+3], 0.f);
        reinterpret_cast<float4*>(out)[idx] = v;
    }
}

// ---------------- launch ----------------
extern "C" void kernel_launch(void* const* d_in, const int* in_sizes, int n_in,
                              void* d_out, int out_size)
{
    const float* x        = (const float*)d_in[0];
    const float* W_sym    = (const float*)d_in[1];
    const float* e_sym    = (const float*)d_in[2];
    const float* W_con    = (const float*)d_in[3];
    const float* e_con    = (const float*)d_in[4];
    const float* W_dis    = (const float*)d_in[5];
    const float* att      = (const float*)d_in[6];
    const float* b_dis    = (const float*)d_in[7];
    const float* cat_w    = (const float*)d_in[8];
    const float* gammas   = (const float*)d_in[9];
    const float* betas    = (const float*)d_in[10];
    const int*   rows_sym = (const int*)d_in[11];
    const int*   cols_sym = (const int*)d_in[12];
    const int*   rows_con = (const int*)d_in[13];
    const int*   cols_con = (const int*)d_in[14];
    int nnz_sym = in_sizes[11];
    int nnz_con = in_sizes[13];

    k_prep<<<3, 256>>>(e_sym, rows_sym, cols_sym, nnz_sym,
                       e_con, rows_con, cols_con, nnz_con,
                       W_sym, W_con, W_dis);
    k_main<<<GRID1, 256>>>(x, att, b_dis);
    k_finalize<<<192, 256>>>(0, gammas, betas);
    k_cat<<<GRID1, 256>>>(cat_w);
    k_finalize<<<64, 256>>>(1, gammas, betas);
    k_out<<<(TOT/4 + 255)/256, 256>>>((float*)d_out);
    (void)n_in; (void)out_size;
}

// round 5
// speedup vs baseline: 2.5010x; 1.1402x over previous
#include <cuda_runtime.h>
#include <cstdint>

typedef unsigned int uint32;

#define NBT   3200          // B*T
#define NND   22
#define NCH   64
#define SLICE (NND*NCH)     // 1408
#define TOT   (NBT*SLICE)
#define MAXNZ 484
#define SPB   4             // slices per block
#define GRID1 (NBT/SPB)     // 800

// ---------------- device scratch ----------------
__device__ float g_hbuf0[TOT];
__device__ float g_hbuf1[TOT];
__device__ float g_hbuf2[TOT];
__device__ float g_pre2[TOT];
__device__ float g_part1[6*64*NBT];
__device__ float g_part2[2*64*NBT];
__device__ float g_scale1[192], g_shift1[192];
__device__ float g_scale2[64],  g_shift2[64];
__device__ float g_Wt[5*4096];          // [g][o][c]
__device__ float g_diag[2][NND*NCH];
__device__ float g_offv[2][MAXNZ*NCH];
__device__ int   g_offcol[2][MAXNZ];
__device__ int   g_rowptr[2][NND+1];

// ---------------- helpers ----------------
__device__ __forceinline__ uint32 tf32(float f){
    uint32 r; asm("cvt.rna.tf32.f32 %0, %1;" : "=r"(r) : "f"(f)); return r;
}
__device__ __forceinline__ void mma_tf32(float c[4], const uint32 a[4], const uint32 b[2]){
    asm volatile("mma.sync.aligned.m16n8k8.row.col.f32.tf32.tf32.f32 "
                 "{%0,%1,%2,%3}, {%4,%5,%6,%7}, {%8,%9}, {%0,%1,%2,%3};"
                 : "+f"(c[0]), "+f"(c[1]), "+f"(c[2]), "+f"(c[3])
                 : "r"(a[0]), "r"(a[1]), "r"(a[2]), "r"(a[3]),
                   "r"(b[0]), "r"(b[1]));
}
__device__ __forceinline__ float redg(float v){  // sum lanes {l, l+4, ..., l+28}
    v += __shfl_down_sync(0xffffffffu, v, 16);
    v += __shfl_down_sync(0xffffffffu, v, 8);
    v += __shfl_down_sync(0xffffffffu, v, 4);
    return v;
}

// ---------------- prep (unchanged, proven) ----------------
__global__ void k_prep(const float* __restrict__ e_sym, const int* __restrict__ rows_sym,
                       const int* __restrict__ cols_sym, int nnz_sym,
                       const float* __restrict__ e_con, const int* __restrict__ rows_con,
                       const int* __restrict__ cols_con, int nnz_con,
                       const float* __restrict__ W_sym, const float* __restrict__ W_con,
                       const float* __restrict__ W_dis)
{
    int blk = blockIdx.x, tid = threadIdx.x;
    if (blk == 2){
        for (int p = tid; p < 5*4096; p += 256){
            int g = p >> 12, rem = p & 4095, c = rem >> 6, o = rem & 63;
            float v;
            if (g < 2)      v = W_sym[g*4096 + c*64 + o];
            else if (g < 4) v = W_con[(g-2)*4096 + c*64 + o];
            else            v = W_dis[c*64 + o];
            g_Wt[g*4096 + o*64 + c] = v;
        }
        return;
    }
    int br = blk;
    const float* e  = br ? e_con   : e_sym;
    const int* rows = br ? rows_con : rows_sym;
    const int* cols = br ? cols_con : cols_sym;
    int nnz         = br ? nnz_con : nnz_sym;

    __shared__ float sden[NND*NCH];
    __shared__ int   smap[512];

    for (int p = tid; p < NND*NCH; p += 256) g_diag[br][p] = 0.f;
    __syncthreads();

    if (tid == 0){
        int m = 0;
        for (int k = 0; k < nnz; k++){
            int r = rows[k], c = cols[k];
            if (c != r){ smap[k] = m; g_offcol[br][m] = c; m++; }
            else smap[k] = -1;
        }
        for (int i = 0; i <= NND; i++){
            int cnt = 0;
            for (int k = 0; k < nnz; k++)
                if (cols[k] != rows[k] && rows[k] < i) cnt++;
            g_rowptr[br][i] = cnt;
        }
    }
    __syncthreads();

    for (int p = tid; p < NND*NCH; p += 256){
        int i = p >> 6, o = p & 63;
        float s = 0.f;
        for (int k = 0; k < nnz; k++)
            if (rows[k] == i) s += expf(e[o*nnz + k]);
        sden[p] = s;
    }
    __syncthreads();

    for (int p = tid; p < 64*nnz; p += 256){
        int k = p >> 6, o = p & 63;
        int r = rows[k];
        float v = expf(e[o*nnz + k]) / sden[r*64 + o];
        int m = smap[k];
        if (m < 0) g_diag[br][r*64 + o] = v;
        else       g_offv[br][m*64 + o] = v;
    }
}

// gemm K=64 from pre-converted tf32 smem (pitch 68), B fragments in registers
__device__ __forceinline__ void mma8t(const uint32* __restrict__ sbuf,
                                      const uint32 (&bwk)[8][2],
                                      int g, int tig, int r2ok,
                                      float acc0[4], float acc1[4]){
#pragma unroll
    for (int k8 = 0; k8 < 8; k8++){
        int c0 = k8*8 + tig, c1 = c0 + 4;
        uint32 a0[4], a1[4];
        a0[0] = sbuf[ g      *68 + c0];
        a0[1] = sbuf[(g + 8) *68 + c0];
        a0[2] = sbuf[ g      *68 + c1];
        a0[3] = sbuf[(g + 8) *68 + c1];
        a1[0] = r2ok ? sbuf[(g + 16)*68 + c0] : 0u;
        a1[1] = 0u;
        a1[2] = r2ok ? sbuf[(g + 16)*68 + c1] : 0u;
        a1[3] = 0u;
        mma_tf32(acc0, a0, bwk[k8]);
        mma_tf32(acc1, a1, bwk[k8]);
    }
}

// gemm K=64, B fragments streamed from global (L2-broadcast hot)
__device__ __forceinline__ void mma8g(const uint32* __restrict__ sbuf,
                                      const float* __restrict__ wg,
                                      int n0, int g, int tig, int r2ok,
                                      float acc0[4], float acc1[4]){
#pragma unroll
    for (int k8 = 0; k8 < 8; k8++){
        const float* wp = wg + (n0 + g)*64 + k8*8 + tig;
        uint32 b[2];
        b[0] = tf32(__ldg(wp));
        b[1] = tf32(__ldg(wp + 4));
        int c0 = k8*8 + tig, c1 = c0 + 4;
        uint32 a0[4], a1[4];
        a0[0] = sbuf[ g      *68 + c0];
        a0[1] = sbuf[(g + 8) *68 + c0];
        a0[2] = sbuf[ g      *68 + c1];
        a0[3] = sbuf[(g + 8) *68 + c1];
        a1[0] = r2ok ? sbuf[(g + 16)*68 + c0] : 0u;
        a1[1] = 0u;
        a1[2] = r2ok ? sbuf[(g + 16)*68 + c1] : 0u;
        a1[3] = 0u;
        mma_tf32(acc0, a0, b);
        mma_tf32(acc1, a1, b);
    }
}

// ---------------- main fused kernel: SPB slices per block ----------------
__global__ __launch_bounds__(256, 2) void k_main(const float* __restrict__ x,
                                                 const float* __restrict__ att,
                                                 const float* __restrict__ b_dis)
{
    __shared__ __align__(16) float  sx   [NND*68];
    __shared__ __align__(16) uint32 sxt  [NND*68];
    __shared__ __align__(16) uint32 sdist[NND*68];
    __shared__ float  sh1 [NND*64];
    __shared__ uint32 sdwT[64*28];
    __shared__ uint32 sattT[NND*24];
    __shared__ int    srp[2][NND+1];
    __shared__ int    socol[2][MAXNZ];
    __shared__ float  sS1[64], sS2[64];

    int tid = threadIdx.x;
    int lane = tid & 31, w = tid >> 5;
    int g = lane >> 2, tig = lane & 3;
    int n0 = w*8;
    int o0 = n0 + 2*tig;
    int r2ok = (g + 16) < NND;

    // persistent B fragments: W1s (1), W1c (3), Wdis (4)
    uint32 bw1s[8][2], bw1c[8][2], bwd[8][2];
#pragma unroll
    for (int k8 = 0; k8 < 8; k8++){
        const float* w1 = g_Wt + 1*4096 + (n0 + g)*64 + k8*8 + tig;
        const float* w3 = g_Wt + 3*4096 + (n0 + g)*64 + k8*8 + tig;
        const float* w4 = g_Wt + 4*4096 + (n0 + g)*64 + k8*8 + tig;
        bw1s[k8][0] = tf32(__ldg(w1)); bw1s[k8][1] = tf32(__ldg(w1 + 4));
        bw1c[k8][0] = tf32(__ldg(w3)); bw1c[k8][1] = tf32(__ldg(w3 + 4));
        bwd [k8][0] = tf32(__ldg(w4)); bwd [k8][1] = tf32(__ldg(w4 + 4));
    }

    // block-constant staging
    for (int p = tid; p < NND*24; p += 256){
        int i = p / 24, c = p % 24;
        sattT[p] = (c < NND) ? tf32(__ldg(&att[i*NND + c])) : 0u;
    }
    for (int p = tid; p < 64*28; p += 256) sdwT[p] = 0u;   // zero padding cols >=22
    for (int p = tid; p < 2*(NND+1); p += 256) srp[p/(NND+1)][p%(NND+1)] = g_rowptr[p/(NND+1)][p%(NND+1)];
    for (int p = tid; p < 2*MAXNZ; p += 256) socol[p/MAXNZ][p%MAXNZ] = g_offcol[p/MAXNZ][p%MAXNZ];

    float2 bd = *(const float2*)&b_dis[o0];

    for (int s = 0; s < SPB; s++){
        int bt = blockIdx.x*SPB + s;
        __syncthreads();   // previous slice fully consumed

        // stage x: fp32 copy + tf32 copy (padded pitch 68)
        const float4* xg = (const float4*)(x + (size_t)bt*SLICE);
        for (int p = tid; p < SLICE/4; p += 256){
            float4 v = __ldg(xg + p);
            int i = p >> 4, c = (p & 15)*4;
            *(float4*)&sx[i*68 + c] = v;
            uint4 t;
            t.x = tf32(v.x); t.y = tf32(v.y); t.z = tf32(v.z); t.w = tf32(v.w);
            *(uint4*)&sxt[i*68 + c] = t;
        }
        __syncthreads();

        if (tid < 64){
            float s1 = 0.f, s2 = 0.f;
#pragma unroll
            for (int i = 0; i < NND; i++){
                float v = sx[i*68 + tid];
                s1 += v; s2 += v*v;
            }
            sS1[tid] = s1; sS2[tid] = s2;
        }
        __syncthreads();

        for (int p = tid; p < SLICE; p += 256){
            int i = p >> 6, c = p & 63;
            float v = sx[i*68 + c];
            float d = sS2[c] - 2.f*v*sS1[c] + (float)NND*v*v;
            sdist[i*68 + c] = tf32(sqrtf(fmaxf(d, 0.f)) + 1e-8f);
        }
        __syncthreads();

        size_t obase = (size_t)bt*SLICE;

        // ===== branches s (br=0) and c (br=1) =====
#pragma unroll
        for (int br = 0; br < 2; br++){
            // h1 gemm -> sh1 (warp-exclusive column stripe)
            float acc0[4] = {0,0,0,0}, acc1[4] = {0,0,0,0};
            if (br == 0) mma8t(sxt, bw1s, g, tig, r2ok, acc0, acc1);
            else         mma8t(sxt, bw1c, g, tig, r2ok, acc0, acc1);
            __syncwarp();
            sh1[ g      *64 + o0    ] = acc0[0];
            sh1[ g      *64 + o0 + 1] = acc0[1];
            sh1[(g + 8) *64 + o0    ] = acc0[2];
            sh1[(g + 8) *64 + o0 + 1] = acc0[3];
            if (r2ok){
                sh1[(g + 16)*64 + o0    ] = acc1[0];
                sh1[(g + 16)*64 + o0 + 1] = acc1[1];
            }
            __syncwarp();

            // h0 gemm (B streamed from L2)
            float h0a[4] = {0,0,0,0}, h0b[4] = {0,0,0,0};
            mma8g(sxt, g_Wt + (br ? 2 : 0)*4096, n0, g, tig, r2ok, h0a, h0b);

            // mix epilogue
            float su0 = 0.f, su1 = 0.f, sq0 = 0.f, sq1 = 0.f;
            int rr[3] = { g, g + 8, g + 16 };
            float va[3] = { h0a[0], h0a[2], h0b[0] };
            float vb[3] = { h0a[1], h0a[3], h0b[1] };
#pragma unroll
            for (int q = 0; q < 3; q++){
                if (q == 2 && !r2ok) break;
                int r = rr[q];
                float2 dg = *(const float2*)&g_diag[br][r*64 + o0];
                float v0 = va[q]*dg.x, v1 = vb[q]*dg.y;
                int mb = srp[br][r], me = srp[br][r+1];
                for (int m = mb; m < me; m++){
                    int cm = socol[br][m];
                    float2 ov = *(const float2*)&g_offv[br][m*64 + o0];
                    v0 += ov.x * sh1[cm*64 + o0];
                    v1 += ov.y * sh1[cm*64 + o0 + 1];
                }
                float2 st = make_float2(v0, v1);
                if (br == 0) *(float2*)&g_hbuf0[obase + r*64 + o0] = st;
                else         *(float2*)&g_hbuf1[obase + r*64 + o0] = st;
                su0 += v0; su1 += v1; sq0 += v0*v0; sq1 += v1*v1;
            }
            su0 = redg(su0); su1 = redg(su1); sq0 = redg(sq0); sq1 = redg(sq1);
            if (lane < 4){
                g_part1[(size_t)((2*br  )*64 + o0    )*NBT + bt] = su0;
                g_part1[(size_t)((2*br  )*64 + o0 + 1)*NBT + bt] = su1;
                g_part1[(size_t)((2*br+1)*64 + o0    )*NBT + bt] = sq0;
                g_part1[(size_t)((2*br+1)*64 + o0 + 1)*NBT + bt] = sq1;
            }
            __syncwarp();
        }

        // ===== z branch: dis @ Wdis, then att @ (that) =====
        {
            float acc0[4] = {0,0,0,0}, acc1[4] = {0,0,0,0};
            mma8t(sdist, bwd, g, tig, r2ok, acc0, acc1);
            __syncwarp();
            // store transposed tf32 for z-mma B
            sdwT[ o0     *28 + g     ] = tf32(acc0[0]);
            sdwT[(o0 + 1)*28 + g     ] = tf32(acc0[1]);
            sdwT[ o0     *28 + g + 8 ] = tf32(acc0[2]);
            sdwT[(o0 + 1)*28 + g + 8 ] = tf32(acc0[3]);
            if (r2ok){
                sdwT[ o0     *28 + g + 16] = tf32(acc1[0]);
                sdwT[(o0 + 1)*28 + g + 16] = tf32(acc1[1]);
            }
            __syncwarp();

            float az0[4] = {0,0,0,0}, az1[4] = {0,0,0,0};
#pragma unroll
            for (int k8 = 0; k8 < 3; k8++){
                int c0 = k8*8 + tig, c1 = c0 + 4;
                uint32 a0[4], a1[4], bz[2];
                a0[0] = sattT[ g      *24 + c0];
                a0[1] = sattT[(g + 8) *24 + c0];
                a0[2] = sattT[ g      *24 + c1];
                a0[3] = sattT[(g + 8) *24 + c1];
                a1[0] = r2ok ? sattT[(g + 16)*24 + c0] : 0u;
                a1[1] = 0u;
                a1[2] = r2ok ? sattT[(g + 16)*24 + c1] : 0u;
                a1[3] = 0u;
                bz[0] = sdwT[(n0 + g)*28 + c0];
                bz[1] = sdwT[(n0 + g)*28 + c1];
                mma_tf32(az0, a0, bz);
                mma_tf32(az1, a1, bz);
            }
            float su0 = 0.f, su1 = 0.f, sq0 = 0.f, sq1 = 0.f;
            int rr[3] = { g, g + 8, g + 16 };
            float va[3] = { az0[0], az0[2], az1[0] };
            float vb[3] = { az0[1], az0[3], az1[1] };
#pragma unroll
            for (int q = 0; q < 3; q++){
                if (q == 2 && !r2ok) break;
                int r = rr[q];
                float v0 = va[q] + bd.x, v1 = vb[q] + bd.y;
                *(float2*)&g_hbuf2[obase + r*64 + o0] = make_float2(v0, v1);
                su0 += v0; su1 += v1; sq0 += v0*v0; sq1 += v1*v1;
            }
            su0 = redg(su0); su1 = redg(su1); sq0 = redg(sq0); sq1 = redg(sq1);
            if (lane < 4){
                g_part1[(size_t)(4*64 + o0    )*NBT + bt] = su0;
                g_part1[(size_t)(4*64 + o0 + 1)*NBT + bt] = su1;
                g_part1[(size_t)(5*64 + o0    )*NBT + bt] = sq0;
                g_part1[(size_t)(5*64 + o0 + 1)*NBT + bt] = sq1;
            }
        }
    }
}

// ---------------- BN stats finalize (unchanged) ----------------
__global__ void k_finalize(int which, const float* __restrict__ gammas,
                           const float* __restrict__ betas)
{
    int ch = blockIdx.x, tid = threadIdx.x;
    int b = ch >> 6, o = ch & 63;
    const float* part = which ? g_part2 : g_part1;
    const float* psum = part + (size_t)((2*b  )*64 + o) * NBT;
    const float* psq  = part + (size_t)((2*b+1)*64 + o) * NBT;
    __shared__ float r1[256], r2[256];
    float s = 0.f, q = 0.f;
    for (int t = tid; t < NBT; t += 256){ s += psum[t]; q += psq[t]; }
    r1[tid] = s; r2[tid] = q;
    __syncthreads();
    for (int off = 128; off; off >>= 1){
        if (tid < off){ r1[tid] += r1[tid+off]; r2[tid] += r2[tid+off]; }
        __syncthreads();
    }
    if (tid == 0){
        const float invM = 1.f / 70400.f;
        float mu  = r1[0]*invM;
        float var = r2[0]*invM - mu*mu;
        int grow = which ? 3 : b;
        float g  = gammas[grow*64 + o], be = betas[grow*64 + o];
        float sc = g * rsqrtf(var + 1e-5f);
        if (which){ g_scale2[o]  = sc; g_shift2[o]  = be - mu*sc; }
        else      { g_scale1[ch] = sc; g_shift1[ch] = be - mu*sc; }
    }
}

// ---------------- BN+ReLU + cat matmul (192->64) + stats ----------------
__global__ __launch_bounds__(256) void k_cat(const float* __restrict__ cat_w)
{
    __shared__ __align__(16) uint32 scat[NND*196];
    __shared__ float ssc[192], ssh[192];

    int tid = threadIdx.x;
    int lane = tid & 31, w = tid >> 5;
    int g = lane >> 2, tig = lane & 3;
    int n0 = w*8;
    int o0 = n0 + 2*tig;
    int r2ok = (g + 16) < NND;

    // persistent B fragments: 24 ksteps x 2
    uint32 bc[24][2];
#pragma unroll
    for (int k8 = 0; k8 < 24; k8++){
        const float* wp = cat_w + (n0 + g)*192 + k8*8 + tig;
        bc[k8][0] = tf32(__ldg(wp));
        bc[k8][1] = tf32(__ldg(wp + 4));
    }
    for (int p = tid; p < 192; p += 256){ ssc[p] = g_scale1[p]; ssh[p] = g_shift1[p]; }

    for (int s = 0; s < SPB; s++){
        int bt = blockIdx.x*SPB + s;
        __syncthreads();

        // stage BN(ReLU(hbuf)) as tf32 into scat (pitch 196)
        const float* bufs[3] = { g_hbuf0, g_hbuf1, g_hbuf2 };
#pragma unroll
        for (int br = 0; br < 3; br++){
            const float4* hb = (const float4*)(bufs[br] + (size_t)bt*SLICE);
            for (int p = tid; p < SLICE/4; p += 256){
                float4 v = __ldg(hb + p);
                int i = p >> 4, c = (p & 15)*4;
                int f = br*64 + c;
                uint32* dst = &scat[i*196 + f];
                dst[0] = tf32(fmaxf(v.x*ssc[f  ] + ssh[f  ], 0.f));
                dst[1] = tf32(fmaxf(v.y*ssc[f+1] + ssh[f+1], 0.f));
                dst[2] = tf32(fmaxf(v.z*ssc[f+2] + ssh[f+2], 0.f));
                dst[3] = tf32(fmaxf(v.w*ssc[f+3] + ssh[f+3], 0.f));
            }
        }
        __syncthreads();

        float acc0[4] = {0,0,0,0}, acc1[4] = {0,0,0,0};
#pragma unroll
        for (int k8 = 0; k8 < 24; k8++){
            int c0 = k8*8 + tig, c1 = c0 + 4;
            uint32 a0[4], a1[4];
            a0[0] = scat[ g      *196 + c0];
            a0[1] = scat[(g + 8) *196 + c0];
            a0[2] = scat[ g      *196 + c1];
            a0[3] = scat[(g + 8) *196 + c1];
            a1[0] = r2ok ? scat[(g + 16)*196 + c0] : 0u;
            a1[1] = 0u;
            a1[2] = r2ok ? scat[(g + 16)*196 + c1] : 0u;
            a1[3] = 0u;
            mma_tf32(acc0, a0, bc[k8]);
            mma_tf32(acc1, a1, bc[k8]);
        }

        float su0 = 0.f, su1 = 0.f, sq0 = 0.f, sq1 = 0.f;
        int rr[3] = { g, g + 8, g + 16 };
        float va[3] = { acc0[0], acc0[2], acc1[0] };
        float vb[3] = { acc0[1], acc0[3], acc1[1] };
        size_t obase = (size_t)bt*SLICE;
#pragma unroll
        for (int q = 0; q < 3; q++){
            if (q == 2 && !r2ok) break;
            int r = rr[q];
            float v0 = va[q], v1 = vb[q];
            *(float2*)&g_pre2[obase + r*64 + o0] = make_float2(v0, v1);
            su0 += v0; su1 += v1; sq0 += v0*v0; sq1 += v1*v1;
        }
        su0 = redg(su0); su1 = redg(su1); sq0 = redg(sq0); sq1 = redg(sq1);
        if (lane < 4){
            g_part2[(size_t)(o0     )*NBT + bt] = su0;
            g_part2[(size_t)(o0 + 1 )*NBT + bt] = su1;
            g_part2[(size_t)(64 + o0    )*NBT + bt] = sq0;
            g_part2[(size_t)(64 + o0 + 1)*NBT + bt] = sq1;
        }
    }
}

// ---------------- final BN+ReLU elementwise ----------------
__global__ void k_out(float* __restrict__ out)
{
    size_t idx = (size_t)blockIdx.x*256 + threadIdx.x;
    if (idx < TOT/4){
        float4 v = reinterpret_cast<const float4*>(g_pre2)[idx];
        int ob = (int)((idx*4) & 63);
        v.x = fmaxf(v.x*g_scale2[ob  ] + g_shift2[ob  ], 0.f);
        v.y = fmaxf(v.y*g_scale2[ob+1] + g_shift2[ob+1], 0.f);
        v.z = fmaxf(v.z*g_scale2[ob+2] + g_shift2[ob+2], 0.f);
        v.w = fmaxf(v.w*g_scale2[ob+3] + g_shift2[ob+3], 0.f);
        reinterpret_cast<float4*>(out)[idx] = v;
    }
}

// ---------------- launch ----------------
extern "C" void kernel_launch(void* const* d_in, const int* in_sizes, int n_in,
                              void* d_out, int out_size)
{
    const float* x        = (const float*)d_in[0];
    const float* W_sym    = (const float*)d_in[1];
    const float* e_sym    = (const float*)d_in[2];
    const float* W_con    = (const float*)d_in[3];
    const float* e_con    = (const float*)d_in[4];
    const float* W_dis    = (const float*)d_in[5];
    const float* att      = (const float*)d_in[6];
    const float* b_dis    = (const float*)d_in[7];
    const float* cat_w    = (const float*)d_in[8];
    const float* gammas   = (const float*)d_in[9];
    const float* betas    = (const float*)d_in[10];
    const int*   rows_sym = (const int*)d_in[11];
    const int*   cols_sym = (const int*)d_in[12];
    const int*   rows_con = (const int*)d_in[13];
    const int*   cols_con = (const int*)d_in[14];
    int nnz_sym = in_sizes[11];
    int nnz_con = in_sizes[13];

    k_prep<<<3, 256>>>(e_sym, rows_sym, cols_sym, nnz_sym,
                       e_con, rows_con, cols_con, nnz_con,
                       W_sym, W_con, W_dis);
    k_main<<<GRID1, 256>>>(x, att, b_dis);
    k_finalize<<<192, 256>>>(0, gammas, betas);
    k_cat<<<GRID1, 256>>>(cat_w);
    k_finalize<<<64, 256>>>(1, gammas, betas);
    k_out<<<(TOT/4 + 255)/256, 256>>>((float*)d_out);
    (void)n_in; (void)out_size;
}

// round 6
// speedup vs baseline: 2.6336x; 1.0530x over previous
#include <cuda_runtime.h>
#include <cstdint>

typedef unsigned int uint32;

#define NBT   3200          // B*T
#define NND   22
#define NCH   64
#define SLICE (NND*NCH)     // 1408
#define TOT   (NBT*SLICE)
#define MAXNZ 484
#define SPB   4             // slices per block
#define GRID1 (NBT/SPB)     // 800
#define OFFCAP0 32          // off-diag capacity branch sym (actual 18)
#define OFFCAP1 96          // off-diag capacity branch con (actual 66)

// ---------------- device scratch ----------------
__device__ float g_hbuf0[TOT];
__device__ float g_hbuf1[TOT];
__device__ float g_hbuf2[TOT];
__device__ float g_pre2[TOT];
__device__ float g_part1[6*64*NBT];
__device__ float g_part2[2*64*NBT];
__device__ float g_scale1[192], g_shift1[192];
__device__ float g_scale2[64],  g_shift2[64];
__device__ float g_Wt[5*4096];          // [g][o][c]
__device__ float g_diag[2][NND*NCH];
__device__ float g_offv[2][MAXNZ*NCH];
__device__ int   g_offcol[2][MAXNZ];
__device__ int   g_rowptr[2][NND+1];

// ---------------- helpers ----------------
__device__ __forceinline__ uint32 tf32(float f){
    uint32 r; asm("cvt.rna.tf32.f32 %0, %1;" : "=r"(r) : "f"(f)); return r;
}
__device__ __forceinline__ void mma_tf32(float c[4], const uint32 a[4], const uint32 b[2]){
    asm volatile("mma.sync.aligned.m16n8k8.row.col.f32.tf32.tf32.f32 "
                 "{%0,%1,%2,%3}, {%4,%5,%6,%7}, {%8,%9}, {%0,%1,%2,%3};"
                 : "+f"(c[0]), "+f"(c[1]), "+f"(c[2]), "+f"(c[3])
                 : "r"(a[0]), "r"(a[1]), "r"(a[2]), "r"(a[3]),
                   "r"(b[0]), "r"(b[1]));
}
__device__ __forceinline__ float redg(float v){
    v += __shfl_down_sync(0xffffffffu, v, 16);
    v += __shfl_down_sync(0xffffffffu, v, 8);
    v += __shfl_down_sync(0xffffffffu, v, 4);
    return v;
}

// ---------------- prep (unchanged, proven) ----------------
__global__ void k_prep(const float* __restrict__ e_sym, const int* __restrict__ rows_sym,
                       const int* __restrict__ cols_sym, int nnz_sym,
                       const float* __restrict__ e_con, const int* __restrict__ rows_con,
                       const int* __restrict__ cols_con, int nnz_con,
                       const float* __restrict__ W_sym, const float* __restrict__ W_con,
                       const float* __restrict__ W_dis)
{
    int blk = blockIdx.x, tid = threadIdx.x;
    if (blk == 2){
        for (int p = tid; p < 5*4096; p += 256){
            int g = p >> 12, rem = p & 4095, c = rem >> 6, o = rem & 63;
            float v;
            if (g < 2)      v = W_sym[g*4096 + c*64 + o];
            else if (g < 4) v = W_con[(g-2)*4096 + c*64 + o];
            else            v = W_dis[c*64 + o];
            g_Wt[g*4096 + o*64 + c] = v;
        }
        return;
    }
    int br = blk;
    const float* e  = br ? e_con   : e_sym;
    const int* rows = br ? rows_con : rows_sym;
    const int* cols = br ? cols_con : cols_sym;
    int nnz         = br ? nnz_con : nnz_sym;

    __shared__ float sden[NND*NCH];
    __shared__ int   smap[512];

    for (int p = tid; p < NND*NCH; p += 256) g_diag[br][p] = 0.f;
    __syncthreads();

    if (tid == 0){
        int m = 0;
        for (int k = 0; k < nnz; k++){
            int r = rows[k], c = cols[k];
            if (c != r){ smap[k] = m; g_offcol[br][m] = c; m++; }
            else smap[k] = -1;
        }
        for (int i = 0; i <= NND; i++){
            int cnt = 0;
            for (int k = 0; k < nnz; k++)
                if (cols[k] != rows[k] && rows[k] < i) cnt++;
            g_rowptr[br][i] = cnt;
        }
    }
    __syncthreads();

    for (int p = tid; p < NND*NCH; p += 256){
        int i = p >> 6, o = p & 63;
        float s = 0.f;
        for (int k = 0; k < nnz; k++)
            if (rows[k] == i) s += expf(e[o*nnz + k]);
        sden[p] = s;
    }
    __syncthreads();

    for (int p = tid; p < 64*nnz; p += 256){
        int k = p >> 6, o = p & 63;
        int r = rows[k];
        float v = expf(e[o*nnz + k]) / sden[r*64 + o];
        int m = smap[k];
        if (m < 0) g_diag[br][r*64 + o] = v;
        else       g_offv[br][m*64 + o] = v;
    }
}

// gemm K=64 from pre-converted tf32 smem (pitch 68), B fragments in registers
__device__ __forceinline__ void mma8t(const uint32* __restrict__ sbuf,
                                      const uint32 (&bwk)[8][2],
                                      int g, int tig, int r2ok,
                                      float acc0[4], float acc1[4]){
#pragma unroll
    for (int k8 = 0; k8 < 8; k8++){
        int c0 = k8*8 + tig, c1 = c0 + 4;
        uint32 a0[4], a1[4];
        a0[0] = sbuf[ g      *68 + c0];
        a0[1] = sbuf[(g + 8) *68 + c0];
        a0[2] = sbuf[ g      *68 + c1];
        a0[3] = sbuf[(g + 8) *68 + c1];
        a1[0] = r2ok ? sbuf[(g + 16)*68 + c0] : 0u;
        a1[1] = 0u;
        a1[2] = r2ok ? sbuf[(g + 16)*68 + c1] : 0u;
        a1[3] = 0u;
        mma_tf32(acc0, a0, bwk[k8]);
        mma_tf32(acc1, a1, bwk[k8]);
    }
}

// gemm K=64, B fragments streamed from global (L2-broadcast hot)
__device__ __forceinline__ void mma8g(const uint32* __restrict__ sbuf,
                                      const float* __restrict__ wg,
                                      int n0, int g, int tig, int r2ok,
                                      float acc0[4], float acc1[4]){
#pragma unroll
    for (int k8 = 0; k8 < 8; k8++){
        const float* wp = wg + (n0 + g)*64 + k8*8 + tig;
        uint32 b[2];
        b[0] = tf32(__ldg(wp));
        b[1] = tf32(__ldg(wp + 4));
        int c0 = k8*8 + tig, c1 = c0 + 4;
        uint32 a0[4], a1[4];
        a0[0] = sbuf[ g      *68 + c0];
        a0[1] = sbuf[(g + 8) *68 + c0];
        a0[2] = sbuf[ g      *68 + c1];
        a0[3] = sbuf[(g + 8) *68 + c1];
        a1[0] = r2ok ? sbuf[(g + 16)*68 + c0] : 0u;
        a1[1] = 0u;
        a1[2] = r2ok ? sbuf[(g + 16)*68 + c1] : 0u;
        a1[3] = 0u;
        mma_tf32(acc0, a0, b);
        mma_tf32(acc1, a1, b);
    }
}

// ---------------- main fused kernel: SPB slices per block, dynamic smem ----------------
__global__ __launch_bounds__(256, 2) void k_main(const float* __restrict__ x,
                                                 const float* __restrict__ att,
                                                 const float* __restrict__ b_dis)
{
    extern __shared__ __align__(16) float smem_[];
    float*  sx    = smem_;                         // 1496 words
    uint32* sxt   = (uint32*)(sx + 1496);          // 1496
    uint32* sdist = sxt + 1496;                    // 1496
    float*  sh1   = (float*)(sdist + 1496);        // 1408
    uint32* sdwT  = (uint32*)(sh1 + 1408);         // 1792 (64*28)
    uint32* sattT = sdwT + 1792;                   // 528 (22*24)
    float*  sdiag = (float*)(sattT + 528);         // 2816 (2*22*64)
    float*  soffv = sdiag + 2816;                  // 8192 ((32+96)*64)
    int*    ssrp  = (int*)(soffv + 8192);          // 48 (2*23 padded)
    int*    ssocol= ssrp + 48;                     // 128
    float*  sS1   = (float*)(ssocol + 128);        // 64
    float*  sS2   = sS1 + 64;                      // 64

    int tid = threadIdx.x;
    int lane = tid & 31, w = tid >> 5;
    int g = lane >> 2, tig = lane & 3;
    int n0 = w*8;
    int o0 = n0 + 2*tig;
    int r2ok = (g + 16) < NND;

    // persistent B fragments: W1s (1), W1c (3), Wdis (4)
    uint32 bw1s[8][2], bw1c[8][2], bwd[8][2];
#pragma unroll
    for (int k8 = 0; k8 < 8; k8++){
        const float* w1 = g_Wt + 1*4096 + (n0 + g)*64 + k8*8 + tig;
        const float* w3 = g_Wt + 3*4096 + (n0 + g)*64 + k8*8 + tig;
        const float* w4 = g_Wt + 4*4096 + (n0 + g)*64 + k8*8 + tig;
        bw1s[k8][0] = tf32(__ldg(w1)); bw1s[k8][1] = tf32(__ldg(w1 + 4));
        bw1c[k8][0] = tf32(__ldg(w3)); bw1c[k8][1] = tf32(__ldg(w3 + 4));
        bwd [k8][0] = tf32(__ldg(w4)); bwd [k8][1] = tf32(__ldg(w4 + 4));
    }

    // ---- block-constant staging (once per block) ----
    for (int p = tid; p < NND*24; p += 256){
        int i = p / 24, c = p % 24;
        sattT[p] = (c < NND) ? tf32(__ldg(&att[i*NND + c])) : 0u;
    }
    for (int p = tid; p < 64*28; p += 256) sdwT[p] = 0u;
    for (int p = tid; p < 2*(NND+1); p += 256) ssrp[(p/(NND+1))*23 + (p%(NND+1))] = g_rowptr[p/(NND+1)][p%(NND+1)];
    for (int p = tid; p < 2*NND*64; p += 256) sdiag[p] = g_diag[p/(NND*64)][p%(NND*64)];
    {
        int cnt0 = g_rowptr[0][NND]; if (cnt0 > OFFCAP0) cnt0 = OFFCAP0;
        int cnt1 = g_rowptr[1][NND]; if (cnt1 > OFFCAP1) cnt1 = OFFCAP1;
        for (int p = tid; p < cnt0*64; p += 256) soffv[p] = g_offv[0][p];
        for (int p = tid; p < cnt1*64; p += 256) soffv[OFFCAP0*64 + p] = g_offv[1][p];
        for (int p = tid; p < cnt0; p += 256) ssocol[p] = g_offcol[0][p];
        for (int p = tid; p < cnt1; p += 256) ssocol[OFFCAP0 + p] = g_offcol[1][p];
    }

    float2 bd = *(const float2*)&b_dis[o0];

    // prefetch slice 0 x into registers
    float4 xr0, xr1;
    {
        const float4* xg = (const float4*)(x + (size_t)(blockIdx.x*SPB)*SLICE);
        xr0 = __ldg(xg + tid);
        xr1 = (tid + 256 < SLICE/4) ? __ldg(xg + tid + 256) : make_float4(0,0,0,0);
    }

    for (int s = 0; s < SPB; s++){
        int bt = blockIdx.x*SPB + s;
        __syncthreads();   // previous slice fully consumed (also covers block-const staging at s=0)

        // write prefetched x (fp32 + tf32, padded pitch 68)
        {
            int i = tid >> 4, c = (tid & 15)*4;
            *(float4*)&sx[i*68 + c] = xr0;
            uint4 t; t.x = tf32(xr0.x); t.y = tf32(xr0.y); t.z = tf32(xr0.z); t.w = tf32(xr0.w);
            *(uint4*)&sxt[i*68 + c] = t;
            if (tid + 256 < SLICE/4){
                int p = tid + 256; i = p >> 4; c = (p & 15)*4;
                *(float4*)&sx[i*68 + c] = xr1;
                uint4 t2; t2.x = tf32(xr1.x); t2.y = tf32(xr1.y); t2.z = tf32(xr1.z); t2.w = tf32(xr1.w);
                *(uint4*)&sxt[i*68 + c] = t2;
            }
        }
        // prefetch next slice's x (latency hidden behind this slice's compute)
        if (s + 1 < SPB){
            const float4* xg = (const float4*)(x + (size_t)(bt + 1)*SLICE);
            xr0 = __ldg(xg + tid);
            if (tid + 256 < SLICE/4) xr1 = __ldg(xg + tid + 256);
        }
        __syncthreads();

        if (tid < 64){
            float s1 = 0.f, s2 = 0.f;
#pragma unroll
            for (int i = 0; i < NND; i++){
                float v = sx[i*68 + tid];
                s1 += v; s2 += v*v;
            }
            sS1[tid] = s1; sS2[tid] = s2;
        }
        __syncthreads();

        for (int p = tid; p < SLICE; p += 256){
            int i = p >> 6, c = p & 63;
            float v = sx[i*68 + c];
            float d = sS2[c] - 2.f*v*sS1[c] + (float)NND*v*v;
            sdist[i*68 + c] = tf32(sqrtf(fmaxf(d, 0.f)) + 1e-8f);
        }
        __syncthreads();

        size_t obase = (size_t)bt*SLICE;

        // ===== branches s (br=0) and c (br=1) =====
#pragma unroll
        for (int br = 0; br < 2; br++){
            // h1 gemm -> sh1 (warp-exclusive column stripe)
            float acc0[4] = {0,0,0,0}, acc1[4] = {0,0,0,0};
            if (br == 0) mma8t(sxt, bw1s, g, tig, r2ok, acc0, acc1);
            else         mma8t(sxt, bw1c, g, tig, r2ok, acc0, acc1);
            __syncwarp();
            sh1[ g      *64 + o0    ] = acc0[0];
            sh1[ g      *64 + o0 + 1] = acc0[1];
            sh1[(g + 8) *64 + o0    ] = acc0[2];
            sh1[(g + 8) *64 + o0 + 1] = acc0[3];
            if (r2ok){
                sh1[(g + 16)*64 + o0    ] = acc1[0];
                sh1[(g + 16)*64 + o0 + 1] = acc1[1];
            }
            __syncwarp();

            // h0 gemm (B streamed from L2)
            float h0a[4] = {0,0,0,0}, h0b[4] = {0,0,0,0};
            mma8g(sxt, g_Wt + (br ? 2 : 0)*4096, n0, g, tig, r2ok, h0a, h0b);

            // mix epilogue — all operands now in shared memory
            int ob = br ? OFFCAP0 : 0;
            float su0 = 0.f, su1 = 0.f, sq0 = 0.f, sq1 = 0.f;
            int rr[3] = { g, g + 8, g + 16 };
            float va[3] = { h0a[0], h0a[2], h0b[0] };
            float vb[3] = { h0a[1], h0a[3], h0b[1] };
#pragma unroll
            for (int q = 0; q < 3; q++){
                if (q == 2 && !r2ok) break;
                int r = rr[q];
                float2 dg = *(const float2*)&sdiag[br*(NND*64) + r*64 + o0];
                float v0 = va[q]*dg.x, v1 = vb[q]*dg.y;
                int mb = ssrp[br*23 + r], me = ssrp[br*23 + r + 1];
                for (int m = mb; m < me; m++){
                    int cm = ssocol[ob + m];
                    float2 ov = *(const float2*)&soffv[(ob + m)*64 + o0];
                    v0 += ov.x * sh1[cm*64 + o0];
                    v1 += ov.y * sh1[cm*64 + o0 + 1];
                }
                float2 st = make_float2(v0, v1);
                if (br == 0) *(float2*)&g_hbuf0[obase + r*64 + o0] = st;
                else         *(float2*)&g_hbuf1[obase + r*64 + o0] = st;
                su0 += v0; su1 += v1; sq0 += v0*v0; sq1 += v1*v1;
            }
            su0 = redg(su0); su1 = redg(su1); sq0 = redg(sq0); sq1 = redg(sq1);
            if (lane < 4){
                g_part1[(size_t)((2*br  )*64 + o0    )*NBT + bt] = su0;
                g_part1[(size_t)((2*br  )*64 + o0 + 1)*NBT + bt] = su1;
                g_part1[(size_t)((2*br+1)*64 + o0    )*NBT + bt] = sq0;
                g_part1[(size_t)((2*br+1)*64 + o0 + 1)*NBT + bt] = sq1;
            }
            __syncwarp();
        }

        // ===== z branch: dis @ Wdis, then att @ (that) =====
        {
            float acc0[4] = {0,0,0,0}, acc1[4] = {0,0,0,0};
            mma8t(sdist, bwd, g, tig, r2ok, acc0, acc1);
            __syncwarp();
            sdwT[ o0     *28 + g     ] = tf32(acc0[0]);
            sdwT[(o0 + 1)*28 + g     ] = tf32(acc0[1]);
            sdwT[ o0     *28 + g + 8 ] = tf32(acc0[2]);
            sdwT[(o0 + 1)*28 + g + 8 ] = tf32(acc0[3]);
            if (r2ok){
                sdwT[ o0     *28 + g + 16] = tf32(acc1[0]);
                sdwT[(o0 + 1)*28 + g + 16] = tf32(acc1[1]);
            }
            __syncwarp();

            float az0[4] = {0,0,0,0}, az1[4] = {0,0,0,0};
#pragma unroll
            for (int k8 = 0; k8 < 3; k8++){
                int c0 = k8*8 + tig, c1 = c0 + 4;
                uint32 a0[4], a1[4], bz[2];
                a0[0] = sattT[ g      *24 + c0];
                a0[1] = sattT[(g + 8) *24 + c0];
                a0[2] = sattT[ g      *24 + c1];
                a0[3] = sattT[(g + 8) *24 + c1];
                a1[0] = r2ok ? sattT[(g + 16)*24 + c0] : 0u;
                a1[1] = 0u;
                a1[2] = r2ok ? sattT[(g + 16)*24 + c1] : 0u;
                a1[3] = 0u;
                bz[0] = sdwT[(n0 + g)*28 + c0];
                bz[1] = sdwT[(n0 + g)*28 + c1];
                mma_tf32(az0, a0, bz);
                mma_tf32(az1, a1, bz);
            }
            float su0 = 0.f, su1 = 0.f, sq0 = 0.f, sq1 = 0.f;
            int rr[3] = { g, g + 8, g + 16 };
            float va[3] = { az0[0], az0[2], az1[0] };
            float vb[3] = { az0[1], az0[3], az1[1] };
#pragma unroll
            for (int q = 0; q < 3; q++){
                if (q == 2 && !r2ok) break;
                int r = rr[q];
                float v0 = va[q] + bd.x, v1 = vb[q] + bd.y;
                *(float2*)&g_hbuf2[obase + r*64 + o0] = make_float2(v0, v1);
                su0 += v0; su1 += v1; sq0 += v0*v0; sq1 += v1*v1;
            }
            su0 = redg(su0); su1 = redg(su1); sq0 = redg(sq0); sq1 = redg(sq1);
            if (lane < 4){
                g_part1[(size_t)(4*64 + o0    )*NBT + bt] = su0;
                g_part1[(size_t)(4*64 + o0 + 1)*NBT + bt] = su1;
                g_part1[(size_t)(5*64 + o0    )*NBT + bt] = sq0;
                g_part1[(size_t)(5*64 + o0 + 1)*NBT + bt] = sq1;
            }
        }
    }
}

// ---------------- BN stats finalize (unchanged) ----------------
__global__ void k_finalize(int which, const float* __restrict__ gammas,
                           const float* __restrict__ betas)
{
    int ch = blockIdx.x, tid = threadIdx.x;
    int b = ch >> 6, o = ch & 63;
    const float* part = which ? g_part2 : g_part1;
    const float* psum = part + (size_t)((2*b  )*64 + o) * NBT;
    const float* psq  = part + (size_t)((2*b+1)*64 + o) * NBT;
    __shared__ float r1[256], r2[256];
    float s = 0.f, q = 0.f;
    for (int t = tid; t < NBT; t += 256){ s += psum[t]; q += psq[t]; }
    r1[tid] = s; r2[tid] = q;
    __syncthreads();
    for (int off = 128; off; off >>= 1){
        if (tid < off){ r1[tid] += r1[tid+off]; r2[tid] += r2[tid+off]; }
        __syncthreads();
    }
    if (tid == 0){
        const float invM = 1.f / 70400.f;
        float mu  = r1[0]*invM;
        float var = r2[0]*invM - mu*mu;
        int grow = which ? 3 : b;
        float g  = gammas[grow*64 + o], be = betas[grow*64 + o];
        float sc = g * rsqrtf(var + 1e-5f);
        if (which){ g_scale2[o]  = sc; g_shift2[o]  = be - mu*sc; }
        else      { g_scale1[ch] = sc; g_shift1[ch] = be - mu*sc; }
    }
}

// ---------------- BN+ReLU + cat matmul (192->64) + stats (unchanged) ----------------
__global__ __launch_bounds__(256) void k_cat(const float* __restrict__ cat_w)
{
    __shared__ __align__(16) uint32 scat[NND*196];
    __shared__ float ssc[192], ssh[192];

    int tid = threadIdx.x;
    int lane = tid & 31, w = tid >> 5;
    int g = lane >> 2, tig = lane & 3;
    int n0 = w*8;
    int o0 = n0 + 2*tig;
    int r2ok = (g + 16) < NND;

    uint32 bc[24][2];
#pragma unroll
    for (int k8 = 0; k8 < 24; k8++){
        const float* wp = cat_w + (n0 + g)*192 + k8*8 + tig;
        bc[k8][0] = tf32(__ldg(wp));
        bc[k8][1] = tf32(__ldg(wp + 4));
    }
    for (int p = tid; p < 192; p += 256){ ssc[p] = g_scale1[p]; ssh[p] = g_shift1[p]; }

    for (int s = 0; s < SPB; s++){
        int bt = blockIdx.x*SPB + s;
        __syncthreads();

        const float* bufs[3] = { g_hbuf0, g_hbuf1, g_hbuf2 };
#pragma unroll
        for (int br = 0; br < 3; br++){
            const float4* hb = (const float4*)(bufs[br] + (size_t)bt*SLICE);
            for (int p = tid; p < SLICE/4; p += 256){
                float4 v = __ldg(hb + p);
                int i = p >> 4, c = (p & 15)*4;
                int f = br*64 + c;
                uint32* dst = &scat[i*196 + f];
                dst[0] = tf32(fmaxf(v.x*ssc[f  ] + ssh[f  ], 0.f));
                dst[1] = tf32(fmaxf(v.y*ssc[f+1] + ssh[f+1], 0.f));
                dst[2] = tf32(fmaxf(v.z*ssc[f+2] + ssh[f+2], 0.f));
                dst[3] = tf32(fmaxf(v.w*ssc[f+3] + ssh[f+3], 0.f));
            }
        }
        __syncthreads();

        float acc0[4] = {0,0,0,0}, acc1[4] = {0,0,0,0};
#pragma unroll
        for (int k8 = 0; k8 < 24; k8++){
            int c0 = k8*8 + tig, c1 = c0 + 4;
            uint32 a0[4], a1[4];
            a0[0] = scat[ g      *196 + c0];
            a0[1] = scat[(g + 8) *196 + c0];
            a0[2] = scat[ g      *196 + c1];
            a0[3] = scat[(g + 8) *196 + c1];
            a1[0] = r2ok ? scat[(g + 16)*196 + c0] : 0u;
            a1[1] = 0u;
            a1[2] = r2ok ? scat[(g + 16)*196 + c1] : 0u;
            a1[3] = 0u;
            mma_tf32(acc0, a0, bc[k8]);
            mma_tf32(acc1, a1, bc[k8]);
        }

        float su0 = 0.f, su1 = 0.f, sq0 = 0.f, sq1 = 0.f;
        int rr[3] = { g, g + 8, g + 16 };
        float va[3] = { acc0[0], acc0[2], acc1[0] };
        float vb[3] = { acc0[1], acc0[3], acc1[1] };
        size_t obase = (size_t)bt*SLICE;
#pragma unroll
        for (int q = 0; q < 3; q++){
            if (q == 2 && !r2ok) break;
            int r = rr[q];
            float v0 = va[q], v1 = vb[q];
            *(float2*)&g_pre2[obase + r*64 + o0] = make_float2(v0, v1);
            su0 += v0; su1 += v1; sq0 += v0*v0; sq1 += v1*v1;
        }
        su0 = redg(su0); su1 = redg(su1); sq0 = redg(sq0); sq1 = redg(sq1);
        if (lane < 4){
            g_part2[(size_t)(o0     )*NBT + bt] = su0;
            g_part2[(size_t)(o0 + 1 )*NBT + bt] = su1;
            g_part2[(size_t)(64 + o0    )*NBT + bt] = sq0;
            g_part2[(size_t)(64 + o0 + 1)*NBT + bt] = sq1;
        }
    }
}

// ---------------- final BN+ReLU elementwise ----------------
__global__ void k_out(float* __restrict__ out)
{
    size_t idx = (size_t)blockIdx.x*256 + threadIdx.x;
    if (idx < TOT/4){
        float4 v = reinterpret_cast<const float4*>(g_pre2)[idx];
        int ob = (int)((idx*4) & 63);
        v.x = fmaxf(v.x*g_scale2[ob  ] + g_shift2[ob  ], 0.f);
        v.y = fmaxf(v.y*g_scale2[ob+1] + g_shift2[ob+1], 0.f);
        v.z = fmaxf(v.z*g_scale2[ob+2] + g_shift2[ob+2], 0.f);
        v.w = fmaxf(v.w*g_scale2[ob+3] + g_shift2[ob+3], 0.f);
        reinterpret_cast<float4*>(out)[idx] = v;
    }
}

// ---------------- launch ----------------
#define KMAIN_SMEM_BYTES (19528*4)

extern "C" void kernel_launch(void* const* d_in, const int* in_sizes, int n_in,
                              void* d_out, int out_size)
{
    const float* x        = (const float*)d_in[0];
    const float* W_sym    = (const float*)d_in[1];
    const float* e_sym    = (const float*)d_in[2];
    const float* W_con    = (const float*)d_in[3];
    const float* e_con    = (const float*)d_in[4];
    const float* W_dis    = (const float*)d_in[5];
    const float* att      = (const float*)d_in[6];
    const float* b_dis    = (const float*)d_in[7];
    const float* cat_w    = (const float*)d_in[8];
    const float* gammas   = (const float*)d_in[9];
    const float* betas    = (const float*)d_in[10];
    const int*   rows_sym = (const int*)d_in[11];
    const int*   cols_sym = (const int*)d_in[12];
    const int*   rows_con = (const int*)d_in[13];
    const int*   cols_con = (const int*)d_in[14];
    int nnz_sym = in_sizes[11];
    int nnz_con = in_sizes[13];

    static int configured = 0;
    if (!configured){
        cudaFuncSetAttribute(k_main, cudaFuncAttributeMaxDynamicSharedMemorySize, KMAIN_SMEM_BYTES);
        configured = 1;
    }

    k_prep<<<3, 256>>>(e_sym, rows_sym, cols_sym, nnz_sym,
                       e_con, rows_con, cols_con, nnz_con,
                       W_sym, W_con, W_dis);
    k_main<<<GRID1, 256, KMAIN_SMEM_BYTES>>>(x, att, b_dis);
    k_finalize<<<192, 256>>>(0, gammas, betas);
    k_cat<<<GRID1, 256>>>(cat_w);
    k_finalize<<<64, 256>>>(1, gammas, betas);
    k_out<<<(TOT/4 + 255)/256, 256>>>((float*)d_out);
    (void)n_in; (void)out_size;
}